// round 13
// baseline (speedup 1.0000x reference)
#include <cuda_runtime.h>
#include <cuda_fp16.h>
#include <math.h>
#include <stdint.h>

#define BB 4
#define SQ 2048
#define SK 2048
#define DD 512
#define HH 8
#define HDIM 64
#define FSCALE 0.125f
#define LOG2E 1.44269504088896f
#define LNEPS 1e-5f

#define OUT_ELEMS ((size_t)BB * SQ * DD)
#define ATTN_ELEMS ((size_t)BB * HH * SQ * (size_t)SK)

#define PS 72     /* smem half-tile row stride (halves): 144B rows */
#define SP 68     /* fp32 staging stride (floats) */

// ---- scratch ----
__device__ float  g_qlin[BB * SQ * DD];
__device__ __half g_qh[BB * SQ * DD];
__device__ __half g_kh[BB * SK * DD];
__device__ __half g_vh[BB * SK * DD];
__device__ __half g_ctxh[BB * SQ * DD];
__device__ __half g_inqh[BB * SQ * DD];
__device__ __half g_inkh[BB * SK * DD];
__device__ __half g_invh[BB * SK * DD];
__device__ __half g_Wqh[DD * DD];
__device__ __half g_Wkh[DD * DD];
__device__ __half g_Wvh[DD * DD];
__device__ __half g_Woh[DD * DD];
__device__ float  g_rowsum[(size_t)BB * HH * SQ];
__device__ float  g_attn_scratch[ATTN_ELEMS];

// ---- helpers ----
__device__ __forceinline__ uint32_t sptr(const void* p) {
    return (uint32_t)__cvta_generic_to_shared(p);
}
__device__ __forceinline__ void cp16(uint32_t dst, const void* src) {
    asm volatile("cp.async.ca.shared.global [%0], [%1], 16;" :: "r"(dst), "l"(src));
}
#define CP_COMMIT() asm volatile("cp.async.commit_group;")
#define CP_WAIT2()  asm volatile("cp.async.wait_group 2;")
#define CP_WAIT1()  asm volatile("cp.async.wait_group 1;")
#define CP_WAIT0()  asm volatile("cp.async.wait_group 0;")

__device__ __forceinline__ float fexp2(float x) {
    float y;
    asm("ex2.approx.f32 %0, %1;" : "=f"(y) : "f"(x));
    return y;
}

__device__ __forceinline__ void mma_f16(float* c, const uint32_t* a, const uint32_t* b) {
    asm volatile(
        "mma.sync.aligned.m16n8k16.row.col.f32.f16.f16.f32 "
        "{%0,%1,%2,%3}, {%4,%5,%6,%7}, {%8,%9}, {%0,%1,%2,%3};"
        : "+f"(c[0]), "+f"(c[1]), "+f"(c[2]), "+f"(c[3])
        : "r"(a[0]), "r"(a[1]), "r"(a[2]), "r"(a[3]), "r"(b[0]), "r"(b[1]));
}

__device__ __forceinline__ void ldmA(uint32_t* a, const __half* base, int row0, int k0, int lane) {
    const __half* p = base + (size_t)(row0 + (lane & 7) + ((lane >> 3) & 1) * 8) * PS
                      + k0 + (lane >> 4) * 8;
    asm volatile("ldmatrix.sync.aligned.m8n8.x4.shared.b16 {%0,%1,%2,%3}, [%4];"
                 : "=r"(a[0]), "=r"(a[1]), "=r"(a[2]), "=r"(a[3]) : "r"(sptr(p)));
}
__device__ __forceinline__ void ldmB2(uint32_t* b, const __half* base, int n0, int k0, int lane) {
    const __half* p = base + (size_t)(n0 + (lane & 7) + (lane >> 4) * 8) * PS
                      + k0 + ((lane >> 3) & 1) * 8;
    asm volatile("ldmatrix.sync.aligned.m8n8.x4.shared.b16 {%0,%1,%2,%3}, [%4];"
                 : "=r"(b[0]), "=r"(b[1]), "=r"(b[2]), "=r"(b[3]) : "r"(sptr(p)));
}
__device__ __forceinline__ void ldmBt2(uint32_t* b, const __half* base, int k0, int n0, int lane) {
    const __half* p = base + (size_t)(k0 + (lane & 7) + ((lane >> 3) & 1) * 8) * PS
                      + n0 + (lane >> 4) * 8;
    asm volatile("ldmatrix.sync.aligned.m8n8.x4.trans.shared.b16 {%0,%1,%2,%3}, [%4];"
                 : "=r"(b[0]), "=r"(b[1]), "=r"(b[2]), "=r"(b[3]) : "r"(sptr(p)));
}

// ============================================================================
// fp32 -> fp16 conversions, merged launches
// ============================================================================
__global__ __launch_bounds__(256) void to_half3_kernel(
    const float* __restrict__ s0, const float* __restrict__ s1,
    const float* __restrict__ s2,
    __half* __restrict__ d0, __half* __restrict__ d1, __half* __restrict__ d2,
    int n4)
{
    const float* s = blockIdx.y == 0 ? s0 : blockIdx.y == 1 ? s1 : s2;
    __half*      d = blockIdx.y == 0 ? d0 : blockIdx.y == 1 ? d1 : d2;
    int i = blockIdx.x * 256 + threadIdx.x;
    if (i < n4) {
        float4 v = ((const float4*)s)[i];
        ((half2*)d)[i * 2]     = __floats2half2_rn(v.x, v.y);
        ((half2*)d)[i * 2 + 1] = __floats2half2_rn(v.z, v.w);
    }
}
__global__ __launch_bounds__(256) void to_half4_kernel(
    const float* __restrict__ s0, const float* __restrict__ s1,
    const float* __restrict__ s2, const float* __restrict__ s3,
    __half* __restrict__ d0, __half* __restrict__ d1,
    __half* __restrict__ d2, __half* __restrict__ d3, int n4)
{
    const float* s = blockIdx.y == 0 ? s0 : blockIdx.y == 1 ? s1
                   : blockIdx.y == 2 ? s2 : s3;
    __half*      d = blockIdx.y == 0 ? d0 : blockIdx.y == 1 ? d1
                   : blockIdx.y == 2 ? d2 : d3;
    int i = blockIdx.x * 256 + threadIdx.x;
    if (i < n4) {
        float4 v = ((const float4*)s)[i];
        ((half2*)d)[i * 2]     = __floats2half2_rn(v.x, v.y);
        ((half2*)d)[i * 2 + 1] = __floats2half2_rn(v.z, v.w);
    }
}

// ============================================================================
// Linear (half inputs): C[M,512] = A@W^T + bias (+res fp32).
// CTA 128x64, k-chunks 64, 3-stage cp.async pipeline. 8 warps, warp 32x32.
// ============================================================================
template <bool ADD_RES, bool WRITE_F, bool WRITE_H>
__global__ __launch_bounds__(256, 2) void linear_kernel(
    const __half* __restrict__ A, const __half* __restrict__ W,
    const float* __restrict__ bias, const float* __restrict__ res,
    float* __restrict__ C, __half* __restrict__ Ch, float hscale)
{
    extern __shared__ char smc[];
    __half* Ah = (__half*)smc;                       // 3 x [128][PS] = 55296 B
    __half* Wh = (__half*)(smc + 3 * 128 * PS * 2);  // 3 x [64][PS]  = 27648 B
    float* stage = (float*)smc;                      // overlay 34816 B

    const int t    = threadIdx.x;
    const int lane = t & 31;
    const int warp = t >> 5;
    const int wm   = warp >> 1;
    const int wn   = warp & 1;
    const int lr   = lane >> 2;
    const int lc   = lane & 3;
    const int row0 = blockIdx.y * 128;
    const int col0 = blockIdx.x * 64;

    const uint32_t ah0 = sptr(Ah);
    const uint32_t wh0 = sptr(Wh);

    // prologue: issue chunks 0, 1
#pragma unroll
    for (int pc = 0; pc < 2; pc++) {
        int k0 = pc * 64;
#pragma unroll
        for (int i = 0; i < 4; i++) {
            int s = t + 256 * i, r = s >> 3, c8 = (s & 7) * 8;
            cp16(ah0 + (pc * 128 * PS + r * PS + c8) * 2,
                 &A[(size_t)(row0 + r) * DD + k0 + c8]);
        }
#pragma unroll
        for (int i = 0; i < 2; i++) {
            int s = t + 256 * i, r = s >> 3, c8 = (s & 7) * 8;
            cp16(wh0 + (pc * 64 * PS + r * PS + c8) * 2,
                 &W[(size_t)(col0 + r) * DD + k0 + c8]);
        }
        CP_COMMIT();
    }

    float acc[2][4][4] = {};

    for (int kc0 = 0; kc0 < 8; kc0++) {
        __syncthreads();   // all warps done with chunk kc0-1 (buffer (kc0+2)%3 reusable)
        if (kc0 + 2 < 8) {
            int k0 = (kc0 + 2) * 64;
            int nb = (kc0 + 2) % 3;
#pragma unroll
            for (int i = 0; i < 4; i++) {
                int s = t + 256 * i, r = s >> 3, c8 = (s & 7) * 8;
                cp16(ah0 + (nb * 128 * PS + r * PS + c8) * 2,
                     &A[(size_t)(row0 + r) * DD + k0 + c8]);
            }
#pragma unroll
            for (int i = 0; i < 2; i++) {
                int s = t + 256 * i, r = s >> 3, c8 = (s & 7) * 8;
                cp16(wh0 + (nb * 64 * PS + r * PS + c8) * 2,
                     &W[(size_t)(col0 + r) * DD + k0 + c8]);
            }
            CP_COMMIT();
            CP_WAIT2();
        } else if (kc0 + 1 < 8) {
            CP_WAIT1();
        } else {
            CP_WAIT0();
        }
        __syncthreads();

        const __half* Ab = Ah + (kc0 % 3) * 128 * PS;
        const __half* Wb = Wh + (kc0 % 3) * 64 * PS;
#pragma unroll
        for (int kc = 0; kc < 4; kc++) {
            uint32_t a[2][4], bfr[2][4];
            ldmA(a[0], Ab, wm * 32,      kc * 16, lane);
            ldmA(a[1], Ab, wm * 32 + 16, kc * 16, lane);
            ldmB2(bfr[0], Wb, wn * 32,      kc * 16, lane);
            ldmB2(bfr[1], Wb, wn * 32 + 16, kc * 16, lane);
#pragma unroll
            for (int mi = 0; mi < 2; mi++)
#pragma unroll
                for (int ni = 0; ni < 4; ni++)
                    mma_f16(acc[mi][ni], a[mi], &bfr[ni >> 1][(ni & 1) * 2]);
        }
    }

    // bias
#pragma unroll
    for (int ni = 0; ni < 4; ni++) {
        int c = col0 + wn * 32 + ni * 8 + lc * 2;
        float b0 = bias[c], b1 = bias[c + 1];
#pragma unroll
        for (int mi = 0; mi < 2; mi++) {
            acc[mi][ni][0] += b0; acc[mi][ni][1] += b1;
            acc[mi][ni][2] += b0; acc[mi][ni][3] += b1;
        }
    }

    // stage + coalesced store
    __syncthreads();
#pragma unroll
    for (int mi = 0; mi < 2; mi++)
#pragma unroll
        for (int ni = 0; ni < 4; ni++) {
            int r = wm * 32 + mi * 16 + lr;
            int c = wn * 32 + ni * 8 + lc * 2;
            stage[r * SP + c]           = acc[mi][ni][0];
            stage[r * SP + c + 1]       = acc[mi][ni][1];
            stage[(r + 8) * SP + c]     = acc[mi][ni][2];
            stage[(r + 8) * SP + c + 1] = acc[mi][ni][3];
        }
    __syncthreads();
#pragma unroll
    for (int i = 0; i < 8; i++) {
        int s = t + 256 * i, r = s >> 4, c4 = (s & 15) * 4;
        float4 v = *(float4*)&stage[r * SP + c4];
        size_t g = (size_t)(row0 + r) * DD + col0 + c4;
        if (ADD_RES) {
            float4 rr = *(const float4*)&res[g];
            v.x += rr.x; v.y += rr.y; v.z += rr.z; v.w += rr.w;
        }
        if (WRITE_F) *(float4*)&C[g] = v;
        if (WRITE_H) {
            *(half2*)&Ch[g]     = __floats2half2_rn(v.x * hscale, v.y * hscale);
            *(half2*)&Ch[g + 2] = __floats2half2_rn(v.z * hscale, v.w * hscale);
        }
    }
}

// ============================================================================
// Flash pass 0: rowsums of exp2(Qs@K^T). 3-stage cp.async K pipeline.
// CTA 128 q x kv 64. 8 warps (4m x 2n).
// ============================================================================
__global__ __launch_bounds__(256, 2) void flash0_kernel(
    const __half* __restrict__ qh, const __half* __restrict__ kh,
    float* __restrict__ rowsum_out)
{
    extern __shared__ char smc[];
    __half* Qh = (__half*)smc;                      // [128][PS] = 18432
    __half* Kh = (__half*)(smc + 128 * PS * 2);     // 3 x [64][PS] = 27648
    float*  red = (float*)(smc + 128 * PS * 2 + 3 * 64 * PS * 2); // [128][2]

    const int bh = blockIdx.y;
    const int b  = bh >> 3;
    const int h  = bh & 7;
    const int q0 = blockIdx.x * 128;

    const int t    = threadIdx.x;
    const int lane = t & 31;
    const int warp = t >> 5;
    const int wm   = warp >> 1;
    const int wn   = warp & 1;
    const int lr   = lane >> 2;
    const int lc   = lane & 3;

    const __half* Qb = qh + (size_t)b * SQ * DD + h * HDIM;
    const __half* Kb = kh + (size_t)b * SK * DD + h * HDIM;
    const uint32_t kh0 = sptr(Kh);

    // Q tile (once)
#pragma unroll
    for (int i = 0; i < 8; i++) {
        int s = t + 256 * i, r = s >> 4, c4 = (s & 15) * 4;
        *(uint2*)&Qh[r * PS + c4] = *(const uint2*)&Qb[(size_t)(q0 + r) * DD + c4];
    }

    // prologue: issue K tiles 0, 1
#pragma unroll
    for (int pc = 0; pc < 2; pc++) {
#pragma unroll
        for (int i = 0; i < 2; i++) {
            int s = t + 256 * i, r = s >> 3, c8 = (s & 7) * 8;
            cp16(kh0 + (pc * 64 * PS + r * PS + c8) * 2,
                 &Kb[(size_t)(pc * 64 + r) * DD + c8]);
        }
        CP_COMMIT();
    }

    const int T = SK / 64;
    float rs[2][2] = {};

    for (int it = 0; it < T; it++) {
        __syncthreads();
        if (it + 2 < T) {
            int kv = (it + 2) * 64;
            int nb = (it + 2) % 3;
#pragma unroll
            for (int i = 0; i < 2; i++) {
                int s = t + 256 * i, r = s >> 3, c8 = (s & 7) * 8;
                cp16(kh0 + (nb * 64 * PS + r * PS + c8) * 2,
                     &Kb[(size_t)(kv + r) * DD + c8]);
            }
            CP_COMMIT();
            CP_WAIT2();
        } else if (it + 1 < T) {
            CP_WAIT1();
        } else {
            CP_WAIT0();
        }
        __syncthreads();

        const __half* Kb_s = Kh + (it % 3) * 64 * PS;
        float acc[2][4][4] = {};
#pragma unroll
        for (int kc = 0; kc < 4; kc++) {
            uint32_t a[2][4], bfr[2][4];
            ldmA(a[0], Qh, wm * 32,      kc * 16, lane);
            ldmA(a[1], Qh, wm * 32 + 16, kc * 16, lane);
            ldmB2(bfr[0], Kb_s, wn * 32,      kc * 16, lane);
            ldmB2(bfr[1], Kb_s, wn * 32 + 16, kc * 16, lane);
#pragma unroll
            for (int mi = 0; mi < 2; mi++)
#pragma unroll
                for (int ni = 0; ni < 4; ni++)
                    mma_f16(acc[mi][ni], a[mi], &bfr[ni >> 1][(ni & 1) * 2]);
        }

#pragma unroll
        for (int mi = 0; mi < 2; mi++)
#pragma unroll
            for (int ni = 0; ni < 4; ni++) {
                rs[mi][0] += fexp2(acc[mi][ni][0]) + fexp2(acc[mi][ni][1]);
                rs[mi][1] += fexp2(acc[mi][ni][2]) + fexp2(acc[mi][ni][3]);
            }
    }

#pragma unroll
    for (int mi = 0; mi < 2; mi++)
#pragma unroll
        for (int hf = 0; hf < 2; hf++) {
            float v = rs[mi][hf];
            v += __shfl_xor_sync(0xFFFFFFFFu, v, 1);
            v += __shfl_xor_sync(0xFFFFFFFFu, v, 2);
            rs[mi][hf] = v;
        }
    if (lc == 0) {
#pragma unroll
        for (int mi = 0; mi < 2; mi++)
#pragma unroll
            for (int hf = 0; hf < 2; hf++)
                red[(wm * 32 + mi * 16 + hf * 8 + lr) * 2 + wn] = rs[mi][hf];
    }
    __syncthreads();
    if (t < 128)
        rowsum_out[(size_t)bh * SQ + q0 + t] = red[t * 2 + 0] + red[t * 2 + 1];
}

// ============================================================================
// Flash pass 1: recompute S, P = exp2*inv; write attn fp32; O += P@V -> ctxh.
// 3-stage cp.async K,V pipeline. CTA 128 q x kv 64. 8 warps (4m x 2n).
// ============================================================================
__global__ __launch_bounds__(256, 2) void flash1_kernel(
    const __half* __restrict__ qh, const __half* __restrict__ kh,
    const __half* __restrict__ vh, const float* __restrict__ rowsum_in,
    float* __restrict__ attn, __half* __restrict__ ctxh)
{
    extern __shared__ char smc[];
    __half* Qh  = (__half*)smc;                        // 18432
    __half* Kh  = (__half*)(smc + 18432);              // 3 x 9216 = 27648
    __half* Vh  = (__half*)(smc + 18432 + 27648);      // 3 x 9216 = 27648
    __half* Psh = (__half*)(smc + 18432 + 55296);      // 18432
    float*  inv = (float*)(smc + 18432 + 55296 + 18432); // 512

    const int bh = blockIdx.y;
    const int b  = bh >> 3;
    const int h  = bh & 7;
    const int q0 = blockIdx.x * 128;

    const int t    = threadIdx.x;
    const int lane = t & 31;
    const int warp = t >> 5;
    const int wm   = warp >> 1;
    const int wn   = warp & 1;
    const int lr   = lane >> 2;
    const int lc   = lane & 3;

    const __half* Qb = qh + (size_t)b * SQ * DD + h * HDIM;
    const __half* Kb = kh + (size_t)b * SK * DD + h * HDIM;
    const __half* Vb = vh + (size_t)b * SK * DD + h * HDIM;
    const uint32_t kh0 = sptr(Kh);
    const uint32_t vh0 = sptr(Vh);

#pragma unroll
    for (int i = 0; i < 8; i++) {
        int s = t + 256 * i, r = s >> 4, c4 = (s & 15) * 4;
        *(uint2*)&Qh[r * PS + c4] = *(const uint2*)&Qb[(size_t)(q0 + r) * DD + c4];
    }
    if (t < 128)
        inv[t] = 1.0f / rowsum_in[(size_t)bh * SQ + q0 + t];

    // prologue: issue K,V tiles 0, 1
#pragma unroll
    for (int pc = 0; pc < 2; pc++) {
#pragma unroll
        for (int i = 0; i < 2; i++) {
            int s = t + 256 * i, r = s >> 3, c8 = (s & 7) * 8;
            cp16(kh0 + (pc * 64 * PS + r * PS + c8) * 2,
                 &Kb[(size_t)(pc * 64 + r) * DD + c8]);
            cp16(vh0 + (pc * 64 * PS + r * PS + c8) * 2,
                 &Vb[(size_t)(pc * 64 + r) * DD + c8]);
        }
        CP_COMMIT();
    }

    const int T = SK / 64;
    float oacc[2][4][4] = {};
    float* arow = attn + ((size_t)bh * SQ + q0) * SK;

    for (int it = 0; it < T; it++) {
        int kv0 = it * 64;
        __syncthreads();
        if (it + 2 < T) {
            int kv = kv0 + 128;
            int nb = (it + 2) % 3;
#pragma unroll
            for (int i = 0; i < 2; i++) {
                int s = t + 256 * i, r = s >> 3, c8 = (s & 7) * 8;
                cp16(kh0 + (nb * 64 * PS + r * PS + c8) * 2, &Kb[(size_t)(kv + r) * DD + c8]);
                cp16(vh0 + (nb * 64 * PS + r * PS + c8) * 2, &Vb[(size_t)(kv + r) * DD + c8]);
            }
            CP_COMMIT();
            CP_WAIT2();
        } else if (it + 1 < T) {
            CP_WAIT1();
        } else {
            CP_WAIT0();
        }
        __syncthreads();

        const __half* Kb_s = Kh + (it % 3) * 64 * PS;
        const __half* Vb_s = Vh + (it % 3) * 64 * PS;

        // GEMM1: S(128x64) = Q @ K^T
        float acc[2][4][4] = {};
#pragma unroll
        for (int kc = 0; kc < 4; kc++) {
            uint32_t a[2][4], bfr[2][4];
            ldmA(a[0], Qh, wm * 32,      kc * 16, lane);
            ldmA(a[1], Qh, wm * 32 + 16, kc * 16, lane);
            ldmB2(bfr[0], Kb_s, wn * 32,      kc * 16, lane);
            ldmB2(bfr[1], Kb_s, wn * 32 + 16, kc * 16, lane);
#pragma unroll
            for (int mi = 0; mi < 2; mi++)
#pragma unroll
                for (int ni = 0; ni < 4; ni++)
                    mma_f16(acc[mi][ni], a[mi], &bfr[ni >> 1][(ni & 1) * 2]);
        }

        // exp2 * inv: attn (fp32 direct, plain vector stores) + Psh (half)
#pragma unroll
        for (int mi = 0; mi < 2; mi++) {
            int r = wm * 32 + mi * 16 + lr;
            float iv0 = inv[r], iv1 = inv[r + 8];
#pragma unroll
            for (int ni = 0; ni < 4; ni++) {
                int c = wn * 32 + ni * 8 + lc * 2;
                float e0 = fexp2(acc[mi][ni][0]) * iv0;
                float e1 = fexp2(acc[mi][ni][1]) * iv0;
                float e2 = fexp2(acc[mi][ni][2]) * iv1;
                float e3 = fexp2(acc[mi][ni][3]) * iv1;
                *(float2*)&arow[(size_t)r * SK + kv0 + c]       = make_float2(e0, e1);
                *(float2*)&arow[(size_t)(r + 8) * SK + kv0 + c] = make_float2(e2, e3);
                *(half2*)&Psh[r * PS + c]       = __floats2half2_rn(e0, e1);
                *(half2*)&Psh[(r + 8) * PS + c] = __floats2half2_rn(e2, e3);
            }
        }
        __syncthreads();

        // GEMM2: O += P(128x64) @ V(64x64)
#pragma unroll
        for (int kc = 0; kc < 4; kc++) {
            uint32_t a[2][4], bfr[2][4];
            ldmA(a[0], Psh, wm * 32,      kc * 16, lane);
            ldmA(a[1], Psh, wm * 32 + 16, kc * 16, lane);
            ldmBt2(bfr[0], Vb_s, kc * 16, wn * 32,      lane);
            ldmBt2(bfr[1], Vb_s, kc * 16, wn * 32 + 16, lane);
#pragma unroll
            for (int mi = 0; mi < 2; mi++)
#pragma unroll
                for (int ni = 0; ni < 4; ni++)
                    mma_f16(oacc[mi][ni], a[mi], &bfr[ni >> 1][(ni & 1) * 2]);
        }
    }

    // O epilogue: half2 stores to ctxh
#pragma unroll
    for (int mi = 0; mi < 2; mi++) {
        size_t r0 = (size_t)b * SQ + q0 + wm * 32 + mi * 16 + lr;
#pragma unroll
        for (int ni = 0; ni < 4; ni++) {
            int c = h * HDIM + wn * 32 + ni * 8 + lc * 2;
            *(half2*)&ctxh[r0 * DD + c]       = __floats2half2_rn(oacc[mi][ni][0], oacc[mi][ni][1]);
            *(half2*)&ctxh[(r0 + 8) * DD + c] = __floats2half2_rn(oacc[mi][ni][2], oacc[mi][ni][3]);
        }
    }
}

// ============================================================================
// LayerNorm: warp-per-row, shuffle-only
// ============================================================================
__global__ __launch_bounds__(256) void ln_kernel(
    float* __restrict__ out, const float* __restrict__ g,
    const float* __restrict__ bta)
{
    const int warp = threadIdx.x >> 5;
    const int lane = threadIdx.x & 31;
    const size_t row = (size_t)blockIdx.x * 8 + warp;
    float* p = out + row * DD;

    float4 v[4];
    float sum = 0.f;
#pragma unroll
    for (int j = 0; j < 4; j++) {
        v[j] = *(const float4*)&p[lane * 4 + j * 128];
        sum += (v[j].x + v[j].y) + (v[j].z + v[j].w);
    }
#pragma unroll
    for (int o = 16; o; o >>= 1) sum += __shfl_xor_sync(0xFFFFFFFFu, sum, o);
    float mu = sum * (1.0f / DD);

    float var = 0.f;
#pragma unroll
    for (int j = 0; j < 4; j++) {
        float dx = v[j].x - mu, dy = v[j].y - mu, dz = v[j].z - mu, dw = v[j].w - mu;
        var += dx * dx + dy * dy + dz * dz + dw * dw;
    }
#pragma unroll
    for (int o = 16; o; o >>= 1) var += __shfl_xor_sync(0xFFFFFFFFu, var, o);
    float rstd = rsqrtf(var * (1.0f / DD) + LNEPS);

#pragma unroll
    for (int j = 0; j < 4; j++) {
        float4 gg = *(const float4*)&g[lane * 4 + j * 128];
        float4 bb = *(const float4*)&bta[lane * 4 + j * 128];
        float4 o;
        o.x = (v[j].x - mu) * rstd * gg.x + bb.x;
        o.y = (v[j].y - mu) * rstd * gg.y + bb.y;
        o.z = (v[j].z - mu) * rstd * gg.z + bb.z;
        o.w = (v[j].w - mu) * rstd * gg.w + bb.w;
        *(float4*)&p[lane * 4 + j * 128] = o;
    }
}

// ============================================================================
// Launch
// ============================================================================
#define SMEM_LIN (3 * 128 * PS * 2 + 3 * 64 * PS * 2)             /* 82944 */
#define SMEM_F0  (128 * PS * 2 + 3 * 64 * PS * 2 + 1024)          /* 47104 */
#define SMEM_F1  (18432 + 27648 + 27648 + 18432 + 512)            /* 92672 */

extern "C" void kernel_launch(void* const* d_in, const int* in_sizes, int n_in,
                              void* d_out, int out_size)
{
    const float* q   = (const float*)d_in[0];
    const float* k   = (const float*)d_in[1];
    const float* v   = (const float*)d_in[2];
    const float* Wq  = (const float*)d_in[3];
    const float* bq  = (const float*)d_in[4];
    const float* Wk  = (const float*)d_in[5];
    const float* bk  = (const float*)d_in[6];
    const float* Wv  = (const float*)d_in[7];
    const float* bv  = (const float*)d_in[8];
    const float* Wo  = (const float*)d_in[9];
    const float* bo  = (const float*)d_in[10];
    const float* lng = (const float*)d_in[11];
    const float* lnb = (const float*)d_in[12];

    float* out = (float*)d_out;

    float *qlin, *attn_scr, *rowsum;
    __half *qh, *kh, *vh, *ctxh, *inqh, *inkh, *invh, *Wqh, *Wkh, *Wvh, *Woh;
    cudaGetSymbolAddress((void**)&qlin, g_qlin);
    cudaGetSymbolAddress((void**)&attn_scr, g_attn_scratch);
    cudaGetSymbolAddress((void**)&rowsum, g_rowsum);
    cudaGetSymbolAddress((void**)&qh, g_qh);
    cudaGetSymbolAddress((void**)&kh, g_kh);
    cudaGetSymbolAddress((void**)&vh, g_vh);
    cudaGetSymbolAddress((void**)&ctxh, g_ctxh);
    cudaGetSymbolAddress((void**)&inqh, g_inqh);
    cudaGetSymbolAddress((void**)&inkh, g_inkh);
    cudaGetSymbolAddress((void**)&invh, g_invh);
    cudaGetSymbolAddress((void**)&Wqh, g_Wqh);
    cudaGetSymbolAddress((void**)&Wkh, g_Wkh);
    cudaGetSymbolAddress((void**)&Wvh, g_Wvh);
    cudaGetSymbolAddress((void**)&Woh, g_Woh);

    float* attn = ((size_t)out_size >= OUT_ELEMS + ATTN_ELEMS)
                      ? out + OUT_ELEMS : attn_scr;

    cudaFuncSetAttribute((const void*)linear_kernel<false, true, true>,
                         cudaFuncAttributeMaxDynamicSharedMemorySize, SMEM_LIN);
    cudaFuncSetAttribute((const void*)linear_kernel<false, false, true>,
                         cudaFuncAttributeMaxDynamicSharedMemorySize, SMEM_LIN);
    cudaFuncSetAttribute((const void*)linear_kernel<true, true, false>,
                         cudaFuncAttributeMaxDynamicSharedMemorySize, SMEM_LIN);
    cudaFuncSetAttribute((const void*)flash0_kernel,
                         cudaFuncAttributeMaxDynamicSharedMemorySize, SMEM_F0);
    cudaFuncSetAttribute((const void*)flash1_kernel,
                         cudaFuncAttributeMaxDynamicSharedMemorySize, SMEM_F1);

    dim3 blk(256);

    // 0) fp16 conversions (2 launches)
    const int NIN4 = (BB * SQ * DD) / 4;
    const int NW4  = (DD * DD) / 4;
    to_half3_kernel<<<dim3((NIN4 + 255) / 256, 3), blk>>>(q, k, v, inqh, inkh, invh, NIN4);
    to_half4_kernel<<<dim3((NW4 + 255) / 256, 4), blk>>>(Wq, Wk, Wv, Wo,
                                                         Wqh, Wkh, Wvh, Woh, NW4);

    // 1) projections
    dim3 gLin(DD / 64, (BB * SQ) / 128);
    linear_kernel<false, true, true><<<gLin, blk, SMEM_LIN>>>(
        inqh, Wqh, bq, nullptr, qlin, qh, FSCALE * LOG2E);
    linear_kernel<false, false, true><<<gLin, blk, SMEM_LIN>>>(
        inkh, Wkh, bk, nullptr, nullptr, kh, 1.0f);
    linear_kernel<false, false, true><<<gLin, blk, SMEM_LIN>>>(
        invh, Wvh, bv, nullptr, nullptr, vh, 1.0f);

    // 2) pass A: row sums
    dim3 gFl(SQ / 128, BB * HH);
    flash0_kernel<<<gFl, blk, SMEM_F0>>>(qh, kh, rowsum);

    // 3) pass B: normalized attn + O = P@V (half ctx)
    flash1_kernel<<<gFl, blk, SMEM_F1>>>(qh, kh, vh, rowsum, attn, ctxh);

    // 4) output projection + residual(q_lin)
    linear_kernel<true, true, false><<<gLin, blk, SMEM_LIN>>>(
        ctxh, Woh, bo, qlin, out, nullptr, 1.0f);

    // 5) layernorm (warp per row)
    ln_kernel<<<(BB * SQ) / 8, blk>>>(out, lng, lnb);
}

// round 14
// speedup vs baseline: 1.0855x; 1.0855x over previous
#include <cuda_runtime.h>
#include <cuda_fp16.h>
#include <math.h>
#include <stdint.h>

#define BB 4
#define SQ 2048
#define SK 2048
#define DD 512
#define HH 8
#define HDIM 64
#define FSCALE 0.125f
#define LOG2E 1.44269504088896f
#define LNEPS 1e-5f

#define OUT_ELEMS ((size_t)BB * SQ * DD)
#define ATTN_ELEMS ((size_t)BB * HH * SQ * (size_t)SK)

#define PS 72     /* smem half-tile row stride (halves): 144B rows */
#define SP 68     /* fp32 staging stride (floats) */

// ---- scratch ----
__device__ float  g_qlin[BB * SQ * DD];
__device__ __half g_qh[BB * SQ * DD];
__device__ __half g_kh[BB * SK * DD];
__device__ __half g_vh[BB * SK * DD];
__device__ __half g_ctxh[BB * SQ * DD];
__device__ __half g_inqh[BB * SQ * DD];
__device__ __half g_inkh[BB * SK * DD];
__device__ __half g_invh[BB * SK * DD];
__device__ __half g_Wqh[DD * DD];
__device__ __half g_Wkh[DD * DD];
__device__ __half g_Wvh[DD * DD];
__device__ __half g_Woh[DD * DD];
__device__ float  g_rowsum[(size_t)BB * HH * SQ];
__device__ float  g_attn_scratch[ATTN_ELEMS];

// ---- helpers ----
__device__ __forceinline__ uint32_t sptr(const void* p) {
    return (uint32_t)__cvta_generic_to_shared(p);
}
__device__ __forceinline__ void cp16(uint32_t dst, const void* src) {
    asm volatile("cp.async.ca.shared.global [%0], [%1], 16;" :: "r"(dst), "l"(src));
}
#define CP_COMMIT() asm volatile("cp.async.commit_group;")
#define CP_WAIT2()  asm volatile("cp.async.wait_group 2;")
#define CP_WAIT1()  asm volatile("cp.async.wait_group 1;")
#define CP_WAIT0()  asm volatile("cp.async.wait_group 0;")

__device__ __forceinline__ float fexp2(float x) {
    float y;
    asm("ex2.approx.f32 %0, %1;" : "=f"(y) : "f"(x));
    return y;
}
__device__ __forceinline__ uint32_t packh2(float a, float b) {
    half2 h = __floats2half2_rn(a, b);
    return *(uint32_t*)&h;
}

__device__ __forceinline__ void mma_f16(float* c, const uint32_t* a, const uint32_t* b) {
    asm volatile(
        "mma.sync.aligned.m16n8k16.row.col.f32.f16.f16.f32 "
        "{%0,%1,%2,%3}, {%4,%5,%6,%7}, {%8,%9}, {%0,%1,%2,%3};"
        : "+f"(c[0]), "+f"(c[1]), "+f"(c[2]), "+f"(c[3])
        : "r"(a[0]), "r"(a[1]), "r"(a[2]), "r"(a[3]), "r"(b[0]), "r"(b[1]));
}

__device__ __forceinline__ void ldmA(uint32_t* a, const __half* base, int row0, int k0, int lane) {
    const __half* p = base + (size_t)(row0 + (lane & 7) + ((lane >> 3) & 1) * 8) * PS
                      + k0 + (lane >> 4) * 8;
    asm volatile("ldmatrix.sync.aligned.m8n8.x4.shared.b16 {%0,%1,%2,%3}, [%4];"
                 : "=r"(a[0]), "=r"(a[1]), "=r"(a[2]), "=r"(a[3]) : "r"(sptr(p)));
}
__device__ __forceinline__ void ldmB2(uint32_t* b, const __half* base, int n0, int k0, int lane) {
    const __half* p = base + (size_t)(n0 + (lane & 7) + (lane >> 4) * 8) * PS
                      + k0 + ((lane >> 3) & 1) * 8;
    asm volatile("ldmatrix.sync.aligned.m8n8.x4.shared.b16 {%0,%1,%2,%3}, [%4];"
                 : "=r"(b[0]), "=r"(b[1]), "=r"(b[2]), "=r"(b[3]) : "r"(sptr(p)));
}
__device__ __forceinline__ void ldmBt2(uint32_t* b, const __half* base, int k0, int n0, int lane) {
    const __half* p = base + (size_t)(k0 + (lane & 7) + ((lane >> 3) & 1) * 8) * PS
                      + n0 + (lane >> 4) * 8;
    asm volatile("ldmatrix.sync.aligned.m8n8.x4.trans.shared.b16 {%0,%1,%2,%3}, [%4];"
                 : "=r"(b[0]), "=r"(b[1]), "=r"(b[2]), "=r"(b[3]) : "r"(sptr(p)));
}

// ============================================================================
// fp32 -> fp16 conversions, merged launches
// ============================================================================
__global__ __launch_bounds__(256) void to_half3_kernel(
    const float* __restrict__ s0, const float* __restrict__ s1,
    const float* __restrict__ s2,
    __half* __restrict__ d0, __half* __restrict__ d1, __half* __restrict__ d2,
    int n4)
{
    const float* s = blockIdx.y == 0 ? s0 : blockIdx.y == 1 ? s1 : s2;
    __half*      d = blockIdx.y == 0 ? d0 : blockIdx.y == 1 ? d1 : d2;
    int i = blockIdx.x * 256 + threadIdx.x;
    if (i < n4) {
        float4 v = ((const float4*)s)[i];
        ((half2*)d)[i * 2]     = __floats2half2_rn(v.x, v.y);
        ((half2*)d)[i * 2 + 1] = __floats2half2_rn(v.z, v.w);
    }
}
__global__ __launch_bounds__(256) void to_half4_kernel(
    const float* __restrict__ s0, const float* __restrict__ s1,
    const float* __restrict__ s2, const float* __restrict__ s3,
    __half* __restrict__ d0, __half* __restrict__ d1,
    __half* __restrict__ d2, __half* __restrict__ d3, int n4)
{
    const float* s = blockIdx.y == 0 ? s0 : blockIdx.y == 1 ? s1
                   : blockIdx.y == 2 ? s2 : s3;
    __half*      d = blockIdx.y == 0 ? d0 : blockIdx.y == 1 ? d1
                   : blockIdx.y == 2 ? d2 : d3;
    int i = blockIdx.x * 256 + threadIdx.x;
    if (i < n4) {
        float4 v = ((const float4*)s)[i];
        ((half2*)d)[i * 2]     = __floats2half2_rn(v.x, v.y);
        ((half2*)d)[i * 2 + 1] = __floats2half2_rn(v.z, v.w);
    }
}

// ============================================================================
// Linear (half inputs): C[M,512] = A@W^T + bias (+res fp32).
// CTA 128x64, k-chunks 64, 3-stage cp.async pipeline. 8 warps, warp 32x32.
// ============================================================================
template <bool ADD_RES, bool WRITE_F, bool WRITE_H>
__global__ __launch_bounds__(256, 2) void linear_kernel(
    const __half* __restrict__ A, const __half* __restrict__ W,
    const float* __restrict__ bias, const float* __restrict__ res,
    float* __restrict__ C, __half* __restrict__ Ch, float hscale)
{
    extern __shared__ char smc[];
    __half* Ah = (__half*)smc;                       // 3 x [128][PS] = 55296 B
    __half* Wh = (__half*)(smc + 3 * 128 * PS * 2);  // 3 x [64][PS]  = 27648 B
    float* stage = (float*)smc;                      // overlay 34816 B

    const int t    = threadIdx.x;
    const int lane = t & 31;
    const int warp = t >> 5;
    const int wm   = warp >> 1;
    const int wn   = warp & 1;
    const int lr   = lane >> 2;
    const int lc   = lane & 3;
    const int row0 = blockIdx.y * 128;
    const int col0 = blockIdx.x * 64;

    const uint32_t ah0 = sptr(Ah);
    const uint32_t wh0 = sptr(Wh);

    // prologue: issue chunks 0, 1
#pragma unroll
    for (int pc = 0; pc < 2; pc++) {
        int k0 = pc * 64;
#pragma unroll
        for (int i = 0; i < 4; i++) {
            int s = t + 256 * i, r = s >> 3, c8 = (s & 7) * 8;
            cp16(ah0 + (pc * 128 * PS + r * PS + c8) * 2,
                 &A[(size_t)(row0 + r) * DD + k0 + c8]);
        }
#pragma unroll
        for (int i = 0; i < 2; i++) {
            int s = t + 256 * i, r = s >> 3, c8 = (s & 7) * 8;
            cp16(wh0 + (pc * 64 * PS + r * PS + c8) * 2,
                 &W[(size_t)(col0 + r) * DD + k0 + c8]);
        }
        CP_COMMIT();
    }

    float acc[2][4][4] = {};

    for (int kc0 = 0; kc0 < 8; kc0++) {
        __syncthreads();
        if (kc0 + 2 < 8) {
            int k0 = (kc0 + 2) * 64;
            int nb = (kc0 + 2) % 3;
#pragma unroll
            for (int i = 0; i < 4; i++) {
                int s = t + 256 * i, r = s >> 3, c8 = (s & 7) * 8;
                cp16(ah0 + (nb * 128 * PS + r * PS + c8) * 2,
                     &A[(size_t)(row0 + r) * DD + k0 + c8]);
            }
#pragma unroll
            for (int i = 0; i < 2; i++) {
                int s = t + 256 * i, r = s >> 3, c8 = (s & 7) * 8;
                cp16(wh0 + (nb * 64 * PS + r * PS + c8) * 2,
                     &W[(size_t)(col0 + r) * DD + k0 + c8]);
            }
            CP_COMMIT();
            CP_WAIT2();
        } else if (kc0 + 1 < 8) {
            CP_WAIT1();
        } else {
            CP_WAIT0();
        }
        __syncthreads();

        const __half* Ab = Ah + (kc0 % 3) * 128 * PS;
        const __half* Wb = Wh + (kc0 % 3) * 64 * PS;
#pragma unroll
        for (int kc = 0; kc < 4; kc++) {
            uint32_t a[2][4], bfr[2][4];
            ldmA(a[0], Ab, wm * 32,      kc * 16, lane);
            ldmA(a[1], Ab, wm * 32 + 16, kc * 16, lane);
            ldmB2(bfr[0], Wb, wn * 32,      kc * 16, lane);
            ldmB2(bfr[1], Wb, wn * 32 + 16, kc * 16, lane);
#pragma unroll
            for (int mi = 0; mi < 2; mi++)
#pragma unroll
                for (int ni = 0; ni < 4; ni++)
                    mma_f16(acc[mi][ni], a[mi], &bfr[ni >> 1][(ni & 1) * 2]);
        }
    }

    // bias
#pragma unroll
    for (int ni = 0; ni < 4; ni++) {
        int c = col0 + wn * 32 + ni * 8 + lc * 2;
        float b0 = bias[c], b1 = bias[c + 1];
#pragma unroll
        for (int mi = 0; mi < 2; mi++) {
            acc[mi][ni][0] += b0; acc[mi][ni][1] += b1;
            acc[mi][ni][2] += b0; acc[mi][ni][3] += b1;
        }
    }

    // stage + coalesced store
    __syncthreads();
#pragma unroll
    for (int mi = 0; mi < 2; mi++)
#pragma unroll
        for (int ni = 0; ni < 4; ni++) {
            int r = wm * 32 + mi * 16 + lr;
            int c = wn * 32 + ni * 8 + lc * 2;
            stage[r * SP + c]           = acc[mi][ni][0];
            stage[r * SP + c + 1]       = acc[mi][ni][1];
            stage[(r + 8) * SP + c]     = acc[mi][ni][2];
            stage[(r + 8) * SP + c + 1] = acc[mi][ni][3];
        }
    __syncthreads();
#pragma unroll
    for (int i = 0; i < 8; i++) {
        int s = t + 256 * i, r = s >> 4, c4 = (s & 15) * 4;
        float4 v = *(float4*)&stage[r * SP + c4];
        size_t g = (size_t)(row0 + r) * DD + col0 + c4;
        if (ADD_RES) {
            float4 rr = *(const float4*)&res[g];
            v.x += rr.x; v.y += rr.y; v.z += rr.z; v.w += rr.w;
        }
        if (WRITE_F) *(float4*)&C[g] = v;
        if (WRITE_H) {
            *(half2*)&Ch[g]     = __floats2half2_rn(v.x * hscale, v.y * hscale);
            *(half2*)&Ch[g + 2] = __floats2half2_rn(v.z * hscale, v.w * hscale);
        }
    }
}

// ============================================================================
// Flash pass 0: rowsums of exp2(Qs@K^T). 3-stage cp.async K pipeline.
// CTA 128 q x kv 64. 8 warps (4m x 2n).
// ============================================================================
__global__ __launch_bounds__(256, 2) void flash0_kernel(
    const __half* __restrict__ qh, const __half* __restrict__ kh,
    float* __restrict__ rowsum_out)
{
    extern __shared__ char smc[];
    __half* Qh = (__half*)smc;                      // [128][PS] = 18432
    __half* Kh = (__half*)(smc + 128 * PS * 2);     // 3 x [64][PS] = 27648
    float*  red = (float*)(smc + 128 * PS * 2 + 3 * 64 * PS * 2); // [128][2]

    const int bh = blockIdx.y;
    const int b  = bh >> 3;
    const int h  = bh & 7;
    const int q0 = blockIdx.x * 128;

    const int t    = threadIdx.x;
    const int lane = t & 31;
    const int warp = t >> 5;
    const int wm   = warp >> 1;
    const int wn   = warp & 1;
    const int lr   = lane >> 2;
    const int lc   = lane & 3;

    const __half* Qb = qh + (size_t)b * SQ * DD + h * HDIM;
    const __half* Kb = kh + (size_t)b * SK * DD + h * HDIM;
    const uint32_t kh0 = sptr(Kh);

    // Q tile (once)
#pragma unroll
    for (int i = 0; i < 8; i++) {
        int s = t + 256 * i, r = s >> 4, c4 = (s & 15) * 4;
        *(uint2*)&Qh[r * PS + c4] = *(const uint2*)&Qb[(size_t)(q0 + r) * DD + c4];
    }

    // prologue: issue K tiles 0, 1
#pragma unroll
    for (int pc = 0; pc < 2; pc++) {
#pragma unroll
        for (int i = 0; i < 2; i++) {
            int s = t + 256 * i, r = s >> 3, c8 = (s & 7) * 8;
            cp16(kh0 + (pc * 64 * PS + r * PS + c8) * 2,
                 &Kb[(size_t)(pc * 64 + r) * DD + c8]);
        }
        CP_COMMIT();
    }

    const int T = SK / 64;
    float rs[2][2] = {};

    for (int it = 0; it < T; it++) {
        __syncthreads();
        if (it + 2 < T) {
            int kv = (it + 2) * 64;
            int nb = (it + 2) % 3;
#pragma unroll
            for (int i = 0; i < 2; i++) {
                int s = t + 256 * i, r = s >> 3, c8 = (s & 7) * 8;
                cp16(kh0 + (nb * 64 * PS + r * PS + c8) * 2,
                     &Kb[(size_t)(kv + r) * DD + c8]);
            }
            CP_COMMIT();
            CP_WAIT2();
        } else if (it + 1 < T) {
            CP_WAIT1();
        } else {
            CP_WAIT0();
        }
        __syncthreads();

        const __half* Kb_s = Kh + (it % 3) * 64 * PS;
        float acc[2][4][4] = {};
#pragma unroll
        for (int kc = 0; kc < 4; kc++) {
            uint32_t a[2][4], bfr[2][4];
            ldmA(a[0], Qh, wm * 32,      kc * 16, lane);
            ldmA(a[1], Qh, wm * 32 + 16, kc * 16, lane);
            ldmB2(bfr[0], Kb_s, wn * 32,      kc * 16, lane);
            ldmB2(bfr[1], Kb_s, wn * 32 + 16, kc * 16, lane);
#pragma unroll
            for (int mi = 0; mi < 2; mi++)
#pragma unroll
                for (int ni = 0; ni < 4; ni++)
                    mma_f16(acc[mi][ni], a[mi], &bfr[ni >> 1][(ni & 1) * 2]);
        }

#pragma unroll
        for (int mi = 0; mi < 2; mi++)
#pragma unroll
            for (int ni = 0; ni < 4; ni++) {
                rs[mi][0] += fexp2(acc[mi][ni][0]) + fexp2(acc[mi][ni][1]);
                rs[mi][1] += fexp2(acc[mi][ni][2]) + fexp2(acc[mi][ni][3]);
            }
    }

#pragma unroll
    for (int mi = 0; mi < 2; mi++)
#pragma unroll
        for (int hf = 0; hf < 2; hf++) {
            float v = rs[mi][hf];
            v += __shfl_xor_sync(0xFFFFFFFFu, v, 1);
            v += __shfl_xor_sync(0xFFFFFFFFu, v, 2);
            rs[mi][hf] = v;
        }
    if (lc == 0) {
#pragma unroll
        for (int mi = 0; mi < 2; mi++)
#pragma unroll
            for (int hf = 0; hf < 2; hf++)
                red[(wm * 32 + mi * 16 + hf * 8 + lr) * 2 + wn] = rs[mi][hf];
    }
    __syncthreads();
    if (t < 128)
        rowsum_out[(size_t)bh * SQ + q0 + t] = red[t * 2 + 0] + red[t * 2 + 1];
}

// ============================================================================
// Flash pass 1: recompute S, P = exp2*inv; write attn fp32; O += P@V via
// REGISTER-FRAGMENT reuse (no Psh smem staging, one barrier per tile).
// Each wn-warp accumulates O over its 32-kv slice across ALL 64 d cols;
// wn pair reduced once at the end via smem. 3-stage cp.async K,V pipeline.
// ============================================================================
__global__ __launch_bounds__(256, 2) void flash1_kernel(
    const __half* __restrict__ qh, const __half* __restrict__ kh,
    const __half* __restrict__ vh, const float* __restrict__ rowsum_in,
    float* __restrict__ attn, __half* __restrict__ ctxh)
{
    extern __shared__ char smc[];
    __half* Qh  = (__half*)smc;                        // 18432
    __half* Kh  = (__half*)(smc + 18432);              // 3 x 9216 = 27648
    __half* Vh  = (__half*)(smc + 18432 + 27648);      // 3 x 9216 = 27648
    float*  inv = (float*)(smc + 18432 + 55296);       // 512
    float* stageO = (float*)(smc + 18432);             // overlay on Kh/Vh (34816 B)

    const int bh = blockIdx.y;
    const int b  = bh >> 3;
    const int h  = bh & 7;
    const int q0 = blockIdx.x * 128;

    const int t    = threadIdx.x;
    const int lane = t & 31;
    const int warp = t >> 5;
    const int wm   = warp >> 1;
    const int wn   = warp & 1;
    const int lr   = lane >> 2;
    const int lc   = lane & 3;

    const __half* Qb = qh + (size_t)b * SQ * DD + h * HDIM;
    const __half* Kb = kh + (size_t)b * SK * DD + h * HDIM;
    const __half* Vb = vh + (size_t)b * SK * DD + h * HDIM;
    const uint32_t kh0 = sptr(Kh);
    const uint32_t vh0 = sptr(Vh);

#pragma unroll
    for (int i = 0; i < 8; i++) {
        int s = t + 256 * i, r = s >> 4, c4 = (s & 15) * 4;
        *(uint2*)&Qh[r * PS + c4] = *(const uint2*)&Qb[(size_t)(q0 + r) * DD + c4];
    }
    if (t < 128)
        inv[t] = 1.0f / rowsum_in[(size_t)bh * SQ + q0 + t];

    // prologue: issue K,V tiles 0, 1
#pragma unroll
    for (int pc = 0; pc < 2; pc++) {
#pragma unroll
        for (int i = 0; i < 2; i++) {
            int s = t + 256 * i, r = s >> 3, c8 = (s & 7) * 8;
            cp16(kh0 + (pc * 64 * PS + r * PS + c8) * 2,
                 &Kb[(size_t)(pc * 64 + r) * DD + c8]);
            cp16(vh0 + (pc * 64 * PS + r * PS + c8) * 2,
                 &Vb[(size_t)(pc * 64 + r) * DD + c8]);
        }
        CP_COMMIT();
    }

    const int T = SK / 64;
    float oacc[2][8][4] = {};   // partial-k O: 32 q-rows x 64 d cols per warp
    float* arow = attn + ((size_t)bh * SQ + q0) * SK;

    for (int it = 0; it < T; it++) {
        int kv0 = it * 64;
        __syncthreads();
        if (it + 2 < T) {
            int kv = kv0 + 128;
            int nb = (it + 2) % 3;
#pragma unroll
            for (int i = 0; i < 2; i++) {
                int s = t + 256 * i, r = s >> 3, c8 = (s & 7) * 8;
                cp16(kh0 + (nb * 64 * PS + r * PS + c8) * 2, &Kb[(size_t)(kv + r) * DD + c8]);
                cp16(vh0 + (nb * 64 * PS + r * PS + c8) * 2, &Vb[(size_t)(kv + r) * DD + c8]);
            }
            CP_COMMIT();
            CP_WAIT2();
        } else if (it + 1 < T) {
            CP_WAIT1();
        } else {
            CP_WAIT0();
        }
        __syncthreads();

        const __half* Kb_s = Kh + (it % 3) * 64 * PS;
        const __half* Vb_s = Vh + (it % 3) * 64 * PS;

        // GEMM1: S(128x64) = Q @ K^T  (warp: 32 q x 32 kv)
        float acc[2][4][4] = {};
#pragma unroll
        for (int kc = 0; kc < 4; kc++) {
            uint32_t a[2][4], bfr[2][4];
            ldmA(a[0], Qh, wm * 32,      kc * 16, lane);
            ldmA(a[1], Qh, wm * 32 + 16, kc * 16, lane);
            ldmB2(bfr[0], Kb_s, wn * 32,      kc * 16, lane);
            ldmB2(bfr[1], Kb_s, wn * 32 + 16, kc * 16, lane);
#pragma unroll
            for (int mi = 0; mi < 2; mi++)
#pragma unroll
                for (int ni = 0; ni < 4; ni++)
                    mma_f16(acc[mi][ni], a[mi], &bfr[ni >> 1][(ni & 1) * 2]);
        }

        // exp2 * inv: write attn (fp32) + pack P directly into A-fragments
        uint32_t pa[2][2][4];   // [mi][k-pair (16 kv each)][4 frag regs]
#pragma unroll
        for (int mi = 0; mi < 2; mi++) {
            int r = wm * 32 + mi * 16 + lr;
            float iv0 = inv[r], iv1 = inv[r + 8];
#pragma unroll
            for (int ni = 0; ni < 4; ni++) {
                int c = wn * 32 + ni * 8 + lc * 2;
                float e0 = fexp2(acc[mi][ni][0]) * iv0;
                float e1 = fexp2(acc[mi][ni][1]) * iv0;
                float e2 = fexp2(acc[mi][ni][2]) * iv1;
                float e3 = fexp2(acc[mi][ni][3]) * iv1;
                *(float2*)&arow[(size_t)r * SK + kv0 + c]       = make_float2(e0, e1);
                *(float2*)&arow[(size_t)(r + 8) * SK + kv0 + c] = make_float2(e2, e3);
                pa[mi][ni >> 1][(ni & 1) * 2 + 0] = packh2(e0, e1);
                pa[mi][ni >> 1][(ni & 1) * 2 + 1] = packh2(e2, e3);
            }
        }

        // GEMM2: O_partial += P(32q x 32kv) @ V(32kv x 64d), no smem for P
#pragma unroll
        for (int pair = 0; pair < 2; pair++) {
            int kk = wn * 32 + pair * 16;
            uint32_t bfr[4][4];
#pragma unroll
            for (int nq = 0; nq < 4; nq++)
                ldmBt2(bfr[nq], Vb_s, kk, nq * 16, lane);
#pragma unroll
            for (int mi = 0; mi < 2; mi++)
#pragma unroll
                for (int nt = 0; nt < 8; nt++)
                    mma_f16(oacc[mi][nt], pa[mi][pair], &bfr[nt >> 1][(nt & 1) * 2]);
        }
    }

    // Reduce O across the wn pair via smem, then store ctxh (wn==0 warps)
    __syncthreads();   // all iterations done; K/V buffers reusable
    if (wn == 1) {
#pragma unroll
        for (int mi = 0; mi < 2; mi++)
#pragma unroll
            for (int nt = 0; nt < 8; nt++) {
                int r = wm * 32 + mi * 16 + lr;
                int c = nt * 8 + lc * 2;
                stageO[r * SP + c]           = oacc[mi][nt][0];
                stageO[r * SP + c + 1]       = oacc[mi][nt][1];
                stageO[(r + 8) * SP + c]     = oacc[mi][nt][2];
                stageO[(r + 8) * SP + c + 1] = oacc[mi][nt][3];
            }
    }
    __syncthreads();
    if (wn == 0) {
#pragma unroll
        for (int mi = 0; mi < 2; mi++) {
            size_t r0 = (size_t)b * SQ + q0 + wm * 32 + mi * 16 + lr;
            int rs = wm * 32 + mi * 16 + lr;
#pragma unroll
            for (int nt = 0; nt < 8; nt++) {
                int c = nt * 8 + lc * 2;
                float o0 = oacc[mi][nt][0] + stageO[rs * SP + c];
                float o1 = oacc[mi][nt][1] + stageO[rs * SP + c + 1];
                float o2 = oacc[mi][nt][2] + stageO[(rs + 8) * SP + c];
                float o3 = oacc[mi][nt][3] + stageO[(rs + 8) * SP + c + 1];
                int cg = h * HDIM + c;
                *(half2*)&ctxh[r0 * DD + cg]       = __floats2half2_rn(o0, o1);
                *(half2*)&ctxh[(r0 + 8) * DD + cg] = __floats2half2_rn(o2, o3);
            }
        }
    }
}

// ============================================================================
// LayerNorm: warp-per-row, shuffle-only
// ============================================================================
__global__ __launch_bounds__(256) void ln_kernel(
    float* __restrict__ out, const float* __restrict__ g,
    const float* __restrict__ bta)
{
    const int warp = threadIdx.x >> 5;
    const int lane = threadIdx.x & 31;
    const size_t row = (size_t)blockIdx.x * 8 + warp;
    float* p = out + row * DD;

    float4 v[4];
    float sum = 0.f;
#pragma unroll
    for (int j = 0; j < 4; j++) {
        v[j] = *(const float4*)&p[lane * 4 + j * 128];
        sum += (v[j].x + v[j].y) + (v[j].z + v[j].w);
    }
#pragma unroll
    for (int o = 16; o; o >>= 1) sum += __shfl_xor_sync(0xFFFFFFFFu, sum, o);
    float mu = sum * (1.0f / DD);

    float var = 0.f;
#pragma unroll
    for (int j = 0; j < 4; j++) {
        float dx = v[j].x - mu, dy = v[j].y - mu, dz = v[j].z - mu, dw = v[j].w - mu;
        var += dx * dx + dy * dy + dz * dz + dw * dw;
    }
#pragma unroll
    for (int o = 16; o; o >>= 1) var += __shfl_xor_sync(0xFFFFFFFFu, var, o);
    float rstd = rsqrtf(var * (1.0f / DD) + LNEPS);

#pragma unroll
    for (int j = 0; j < 4; j++) {
        float4 gg = *(const float4*)&g[lane * 4 + j * 128];
        float4 bb = *(const float4*)&bta[lane * 4 + j * 128];
        float4 o;
        o.x = (v[j].x - mu) * rstd * gg.x + bb.x;
        o.y = (v[j].y - mu) * rstd * gg.y + bb.y;
        o.z = (v[j].z - mu) * rstd * gg.z + bb.z;
        o.w = (v[j].w - mu) * rstd * gg.w + bb.w;
        *(float4*)&p[lane * 4 + j * 128] = o;
    }
}

// ============================================================================
// Launch
// ============================================================================
#define SMEM_LIN (3 * 128 * PS * 2 + 3 * 64 * PS * 2)             /* 82944 */
#define SMEM_F0  (128 * PS * 2 + 3 * 64 * PS * 2 + 1024)          /* 47104 */
#define SMEM_F1  (18432 + 27648 + 27648 + 512)                    /* 74240 */

extern "C" void kernel_launch(void* const* d_in, const int* in_sizes, int n_in,
                              void* d_out, int out_size)
{
    const float* q   = (const float*)d_in[0];
    const float* k   = (const float*)d_in[1];
    const float* v   = (const float*)d_in[2];
    const float* Wq  = (const float*)d_in[3];
    const float* bq  = (const float*)d_in[4];
    const float* Wk  = (const float*)d_in[5];
    const float* bk  = (const float*)d_in[6];
    const float* Wv  = (const float*)d_in[7];
    const float* bv  = (const float*)d_in[8];
    const float* Wo  = (const float*)d_in[9];
    const float* bo  = (const float*)d_in[10];
    const float* lng = (const float*)d_in[11];
    const float* lnb = (const float*)d_in[12];

    float* out = (float*)d_out;

    float *qlin, *attn_scr, *rowsum;
    __half *qh, *kh, *vh, *ctxh, *inqh, *inkh, *invh, *Wqh, *Wkh, *Wvh, *Woh;
    cudaGetSymbolAddress((void**)&qlin, g_qlin);
    cudaGetSymbolAddress((void**)&attn_scr, g_attn_scratch);
    cudaGetSymbolAddress((void**)&rowsum, g_rowsum);
    cudaGetSymbolAddress((void**)&qh, g_qh);
    cudaGetSymbolAddress((void**)&kh, g_kh);
    cudaGetSymbolAddress((void**)&vh, g_vh);
    cudaGetSymbolAddress((void**)&ctxh, g_ctxh);
    cudaGetSymbolAddress((void**)&inqh, g_inqh);
    cudaGetSymbolAddress((void**)&inkh, g_inkh);
    cudaGetSymbolAddress((void**)&invh, g_invh);
    cudaGetSymbolAddress((void**)&Wqh, g_Wqh);
    cudaGetSymbolAddress((void**)&Wkh, g_Wkh);
    cudaGetSymbolAddress((void**)&Wvh, g_Wvh);
    cudaGetSymbolAddress((void**)&Woh, g_Woh);

    float* attn = ((size_t)out_size >= OUT_ELEMS + ATTN_ELEMS)
                      ? out + OUT_ELEMS : attn_scr;

    cudaFuncSetAttribute((const void*)linear_kernel<false, true, true>,
                         cudaFuncAttributeMaxDynamicSharedMemorySize, SMEM_LIN);
    cudaFuncSetAttribute((const void*)linear_kernel<false, false, true>,
                         cudaFuncAttributeMaxDynamicSharedMemorySize, SMEM_LIN);
    cudaFuncSetAttribute((const void*)linear_kernel<true, true, false>,
                         cudaFuncAttributeMaxDynamicSharedMemorySize, SMEM_LIN);
    cudaFuncSetAttribute((const void*)flash0_kernel,
                         cudaFuncAttributeMaxDynamicSharedMemorySize, SMEM_F0);
    cudaFuncSetAttribute((const void*)flash1_kernel,
                         cudaFuncAttributeMaxDynamicSharedMemorySize, SMEM_F1);

    dim3 blk(256);

    // 0) fp16 conversions (2 launches)
    const int NIN4 = (BB * SQ * DD) / 4;
    const int NW4  = (DD * DD) / 4;
    to_half3_kernel<<<dim3((NIN4 + 255) / 256, 3), blk>>>(q, k, v, inqh, inkh, invh, NIN4);
    to_half4_kernel<<<dim3((NW4 + 255) / 256, 4), blk>>>(Wq, Wk, Wv, Wo,
                                                         Wqh, Wkh, Wvh, Woh, NW4);

    // 1) projections
    dim3 gLin(DD / 64, (BB * SQ) / 128);
    linear_kernel<false, true, true><<<gLin, blk, SMEM_LIN>>>(
        inqh, Wqh, bq, nullptr, qlin, qh, FSCALE * LOG2E);
    linear_kernel<false, false, true><<<gLin, blk, SMEM_LIN>>>(
        inkh, Wkh, bk, nullptr, nullptr, kh, 1.0f);
    linear_kernel<false, false, true><<<gLin, blk, SMEM_LIN>>>(
        invh, Wvh, bv, nullptr, nullptr, vh, 1.0f);

    // 2) pass A: row sums
    dim3 gFl(SQ / 128, BB * HH);
    flash0_kernel<<<gFl, blk, SMEM_F0>>>(qh, kh, rowsum);

    // 3) pass B: normalized attn + O = P@V (register-fragment reuse)
    flash1_kernel<<<gFl, blk, SMEM_F1>>>(qh, kh, vh, rowsum, attn, ctxh);

    // 4) output projection + residual(q_lin)
    linear_kernel<true, true, false><<<gLin, blk, SMEM_LIN>>>(
        ctxh, Woh, bo, qlin, out, nullptr, 1.0f);

    // 5) layernorm (warp per row)
    ln_kernel<<<(BB * SQ) / 8, blk>>>(out, lng, lnb);
}

// round 15
// speedup vs baseline: 1.1277x; 1.0389x over previous
#include <cuda_runtime.h>
#include <cuda_fp16.h>
#include <math.h>
#include <stdint.h>

#define BB 4
#define SQ 2048
#define SK 2048
#define DD 512
#define HH 8
#define HDIM 64
#define FSCALE 0.125f
#define LOG2E 1.44269504088896f
#define LNEPS 1e-5f

#define OUT_ELEMS ((size_t)BB * SQ * DD)
#define ATTN_ELEMS ((size_t)BB * HH * SQ * (size_t)SK)

#define PS 72     /* smem half-tile row stride (halves): 144B rows */
#define SP 68     /* fp32 staging stride (floats), <=64 cols */
#define SPL 132   /* fp32 staging stride for 128-col epilogue */

// ---- scratch ----
__device__ float  g_qlin[BB * SQ * DD];
__device__ __half g_qh[BB * SQ * DD];
__device__ __half g_kh[BB * SK * DD];
__device__ __half g_vh[BB * SK * DD];
__device__ __half g_ctxh[BB * SQ * DD];
__device__ __half g_inqh[BB * SQ * DD];
__device__ __half g_inkh[BB * SK * DD];
__device__ __half g_invh[BB * SK * DD];
__device__ __half g_Wqh[DD * DD];
__device__ __half g_Wkh[DD * DD];
__device__ __half g_Wvh[DD * DD];
__device__ __half g_Woh[DD * DD];
__device__ float  g_rowsum[(size_t)BB * HH * SQ];
__device__ float  g_attn_scratch[ATTN_ELEMS];

// ---- helpers ----
__device__ __forceinline__ uint32_t sptr(const void* p) {
    return (uint32_t)__cvta_generic_to_shared(p);
}
__device__ __forceinline__ void cp16(uint32_t dst, const void* src) {
    asm volatile("cp.async.ca.shared.global [%0], [%1], 16;" :: "r"(dst), "l"(src));
}
#define CP_COMMIT() asm volatile("cp.async.commit_group;")
#define CP_WAIT2()  asm volatile("cp.async.wait_group 2;")
#define CP_WAIT1()  asm volatile("cp.async.wait_group 1;")
#define CP_WAIT0()  asm volatile("cp.async.wait_group 0;")

__device__ __forceinline__ float fexp2(float x) {
    float y;
    asm("ex2.approx.f32 %0, %1;" : "=f"(y) : "f"(x));
    return y;
}
__device__ __forceinline__ uint32_t packh2(float a, float b) {
    half2 h = __floats2half2_rn(a, b);
    return *(uint32_t*)&h;
}

__device__ __forceinline__ void mma_f16(float* c, const uint32_t* a, const uint32_t* b) {
    asm volatile(
        "mma.sync.aligned.m16n8k16.row.col.f32.f16.f16.f32 "
        "{%0,%1,%2,%3}, {%4,%5,%6,%7}, {%8,%9}, {%0,%1,%2,%3};"
        : "+f"(c[0]), "+f"(c[1]), "+f"(c[2]), "+f"(c[3])
        : "r"(a[0]), "r"(a[1]), "r"(a[2]), "r"(a[3]), "r"(b[0]), "r"(b[1]));
}

__device__ __forceinline__ void ldmA(uint32_t* a, const __half* base, int row0, int k0, int lane) {
    const __half* p = base + (size_t)(row0 + (lane & 7) + ((lane >> 3) & 1) * 8) * PS
                      + k0 + (lane >> 4) * 8;
    asm volatile("ldmatrix.sync.aligned.m8n8.x4.shared.b16 {%0,%1,%2,%3}, [%4];"
                 : "=r"(a[0]), "=r"(a[1]), "=r"(a[2]), "=r"(a[3]) : "r"(sptr(p)));
}
__device__ __forceinline__ void ldmB2(uint32_t* b, const __half* base, int n0, int k0, int lane) {
    const __half* p = base + (size_t)(n0 + (lane & 7) + (lane >> 4) * 8) * PS
                      + k0 + ((lane >> 3) & 1) * 8;
    asm volatile("ldmatrix.sync.aligned.m8n8.x4.shared.b16 {%0,%1,%2,%3}, [%4];"
                 : "=r"(b[0]), "=r"(b[1]), "=r"(b[2]), "=r"(b[3]) : "r"(sptr(p)));
}
__device__ __forceinline__ void ldmBt2(uint32_t* b, const __half* base, int k0, int n0, int lane) {
    const __half* p = base + (size_t)(k0 + (lane & 7) + ((lane >> 3) & 1) * 8) * PS
                      + n0 + (lane >> 4) * 8;
    asm volatile("ldmatrix.sync.aligned.m8n8.x4.trans.shared.b16 {%0,%1,%2,%3}, [%4];"
                 : "=r"(b[0]), "=r"(b[1]), "=r"(b[2]), "=r"(b[3]) : "r"(sptr(p)));
}

// ============================================================================
// fp32 -> fp16 conversions, merged launches
// ============================================================================
__global__ __launch_bounds__(256) void to_half3_kernel(
    const float* __restrict__ s0, const float* __restrict__ s1,
    const float* __restrict__ s2,
    __half* __restrict__ d0, __half* __restrict__ d1, __half* __restrict__ d2,
    int n4)
{
    const float* s = blockIdx.y == 0 ? s0 : blockIdx.y == 1 ? s1 : s2;
    __half*      d = blockIdx.y == 0 ? d0 : blockIdx.y == 1 ? d1 : d2;
    int i = blockIdx.x * 256 + threadIdx.x;
    if (i < n4) {
        float4 v = ((const float4*)s)[i];
        ((half2*)d)[i * 2]     = __floats2half2_rn(v.x, v.y);
        ((half2*)d)[i * 2 + 1] = __floats2half2_rn(v.z, v.w);
    }
}
__global__ __launch_bounds__(256) void to_half4_kernel(
    const float* __restrict__ s0, const float* __restrict__ s1,
    const float* __restrict__ s2, const float* __restrict__ s3,
    __half* __restrict__ d0, __half* __restrict__ d1,
    __half* __restrict__ d2, __half* __restrict__ d3, int n4)
{
    const float* s = blockIdx.y == 0 ? s0 : blockIdx.y == 1 ? s1
                   : blockIdx.y == 2 ? s2 : s3;
    __half*      d = blockIdx.y == 0 ? d0 : blockIdx.y == 1 ? d1
                   : blockIdx.y == 2 ? d2 : d3;
    int i = blockIdx.x * 256 + threadIdx.x;
    if (i < n4) {
        float4 v = ((const float4*)s)[i];
        ((half2*)d)[i * 2]     = __floats2half2_rn(v.x, v.y);
        ((half2*)d)[i * 2 + 1] = __floats2half2_rn(v.z, v.w);
    }
}

// ============================================================================
// Linear (half inputs): C[M,512] = A@W^T + bias (+res fp32).
// CTA 128(M) x 128(N), k-chunks 64, 2-stage cp.async. 8 warps, warp 32x64.
// ============================================================================
template <bool ADD_RES, bool WRITE_F, bool WRITE_H>
__global__ __launch_bounds__(256, 2) void linear_kernel(
    const __half* __restrict__ A, const __half* __restrict__ W,
    const float* __restrict__ bias, const float* __restrict__ res,
    float* __restrict__ C, __half* __restrict__ Ch, float hscale)
{
    extern __shared__ char smc[];
    __half* Ah = (__half*)smc;                       // 2 x [128][PS] = 36864 B
    __half* Wh = (__half*)(smc + 2 * 128 * PS * 2);  // 2 x [128][PS] = 36864 B
    float* stage = (float*)smc;                      // overlay [128][SPL] = 67584 B

    const int t    = threadIdx.x;
    const int lane = t & 31;
    const int warp = t >> 5;
    const int wm   = warp >> 1;       // 0..3, 32 rows
    const int wn   = warp & 1;        // 0..1, 64 cols
    const int lr   = lane >> 2;
    const int lc   = lane & 3;
    const int row0 = blockIdx.y * 128;
    const int col0 = blockIdx.x * 128;

    const uint32_t ah0 = sptr(Ah);
    const uint32_t wh0 = sptr(Wh);

    // issue chunk 0
    {
#pragma unroll
        for (int i = 0; i < 4; i++) {
            int s = t + 256 * i, r = s >> 3, c8 = (s & 7) * 8;
            cp16(ah0 + (r * PS + c8) * 2, &A[(size_t)(row0 + r) * DD + c8]);
            cp16(wh0 + (r * PS + c8) * 2, &W[(size_t)(col0 + r) * DD + c8]);
        }
        CP_COMMIT();
    }

    float acc[2][8][4] = {};

    for (int kc0 = 0; kc0 < 8; kc0++) {
        __syncthreads();
        if (kc0 + 1 < 8) {
            int k0 = (kc0 + 1) * 64;
            int nb = (kc0 + 1) & 1;
#pragma unroll
            for (int i = 0; i < 4; i++) {
                int s = t + 256 * i, r = s >> 3, c8 = (s & 7) * 8;
                cp16(ah0 + (nb * 128 * PS + r * PS + c8) * 2,
                     &A[(size_t)(row0 + r) * DD + k0 + c8]);
                cp16(wh0 + (nb * 128 * PS + r * PS + c8) * 2,
                     &W[(size_t)(col0 + r) * DD + k0 + c8]);
            }
            CP_COMMIT();
            CP_WAIT1();
        } else {
            CP_WAIT0();
        }
        __syncthreads();

        const __half* Ab = Ah + (kc0 & 1) * 128 * PS;
        const __half* Wb = Wh + (kc0 & 1) * 128 * PS;
#pragma unroll
        for (int kc = 0; kc < 4; kc++) {
            uint32_t a[2][4], bfr[4][4];
            ldmA(a[0], Ab, wm * 32,      kc * 16, lane);
            ldmA(a[1], Ab, wm * 32 + 16, kc * 16, lane);
#pragma unroll
            for (int nt = 0; nt < 4; nt++)
                ldmB2(bfr[nt], Wb, wn * 64 + nt * 16, kc * 16, lane);
#pragma unroll
            for (int mi = 0; mi < 2; mi++)
#pragma unroll
                for (int ni = 0; ni < 8; ni++)
                    mma_f16(acc[mi][ni], a[mi], &bfr[ni >> 1][(ni & 1) * 2]);
        }
    }

    // bias
#pragma unroll
    for (int ni = 0; ni < 8; ni++) {
        int c = col0 + wn * 64 + ni * 8 + lc * 2;
        float b0 = bias[c], b1 = bias[c + 1];
#pragma unroll
        for (int mi = 0; mi < 2; mi++) {
            acc[mi][ni][0] += b0; acc[mi][ni][1] += b1;
            acc[mi][ni][2] += b0; acc[mi][ni][3] += b1;
        }
    }

    // stage + coalesced store (stride SPL for 128 cols)
    __syncthreads();
#pragma unroll
    for (int mi = 0; mi < 2; mi++)
#pragma unroll
        for (int ni = 0; ni < 8; ni++) {
            int r = wm * 32 + mi * 16 + lr;
            int c = wn * 64 + ni * 8 + lc * 2;
            stage[r * SPL + c]           = acc[mi][ni][0];
            stage[r * SPL + c + 1]       = acc[mi][ni][1];
            stage[(r + 8) * SPL + c]     = acc[mi][ni][2];
            stage[(r + 8) * SPL + c + 1] = acc[mi][ni][3];
        }
    __syncthreads();
#pragma unroll
    for (int i = 0; i < 16; i++) {
        int s = t + 256 * i, r = s >> 5, c4 = (s & 31) * 4;
        float4 v = *(float4*)&stage[r * SPL + c4];
        size_t g = (size_t)(row0 + r) * DD + col0 + c4;
        if (ADD_RES) {
            float4 rr = *(const float4*)&res[g];
            v.x += rr.x; v.y += rr.y; v.z += rr.z; v.w += rr.w;
        }
        if (WRITE_F) *(float4*)&C[g] = v;
        if (WRITE_H) {
            *(half2*)&Ch[g]     = __floats2half2_rn(v.x * hscale, v.y * hscale);
            *(half2*)&Ch[g + 2] = __floats2half2_rn(v.z * hscale, v.w * hscale);
        }
    }
}

// ============================================================================
// Flash pass 0: rowsums of exp2(Qs@K^T). kv tiles of 128, 2-stage cp.async.
// CTA 128 q x kv 128. 8 warps (4m x 2n), warp 32q x 64kv.
// ============================================================================
__global__ __launch_bounds__(256, 2) void flash0_kernel(
    const __half* __restrict__ qh, const __half* __restrict__ kh,
    float* __restrict__ rowsum_out)
{
    extern __shared__ char smc[];
    __half* Qh = (__half*)smc;                      // [128][PS] = 18432
    __half* Kh = (__half*)(smc + 128 * PS * 2);     // 2 x [128][PS] = 36864
    float*  red = (float*)(smc + 128 * PS * 2 + 2 * 128 * PS * 2); // [128][2]

    const int bh = blockIdx.y;
    const int b  = bh >> 3;
    const int h  = bh & 7;
    const int q0 = blockIdx.x * 128;

    const int t    = threadIdx.x;
    const int lane = t & 31;
    const int warp = t >> 5;
    const int wm   = warp >> 1;
    const int wn   = warp & 1;
    const int lr   = lane >> 2;
    const int lc   = lane & 3;

    const __half* Qb = qh + (size_t)b * SQ * DD + h * HDIM;
    const __half* Kb = kh + (size_t)b * SK * DD + h * HDIM;
    const uint32_t kh0 = sptr(Kh);

    // Q tile (once)
#pragma unroll
    for (int i = 0; i < 8; i++) {
        int s = t + 256 * i, r = s >> 4, c4 = (s & 15) * 4;
        *(uint2*)&Qh[r * PS + c4] = *(const uint2*)&Qb[(size_t)(q0 + r) * DD + c4];
    }

    // issue K tile 0 (128 rows)
#pragma unroll
    for (int i = 0; i < 4; i++) {
        int s = t + 256 * i, r = s >> 3, c8 = (s & 7) * 8;
        cp16(kh0 + (r * PS + c8) * 2, &Kb[(size_t)r * DD + c8]);
    }
    CP_COMMIT();

    const int T = SK / 128;   // 16
    float rs[2][2] = {};

    for (int it = 0; it < T; it++) {
        __syncthreads();
        if (it + 1 < T) {
            int kv = (it + 1) * 128;
            int nb = (it + 1) & 1;
#pragma unroll
            for (int i = 0; i < 4; i++) {
                int s = t + 256 * i, r = s >> 3, c8 = (s & 7) * 8;
                cp16(kh0 + (nb * 128 * PS + r * PS + c8) * 2,
                     &Kb[(size_t)(kv + r) * DD + c8]);
            }
            CP_COMMIT();
            CP_WAIT1();
        } else {
            CP_WAIT0();
        }
        __syncthreads();

        const __half* Kb_s = Kh + (it & 1) * 128 * PS;
        float acc[2][8][4] = {};
#pragma unroll
        for (int kc = 0; kc < 4; kc++) {
            uint32_t a[2][4], bfr[4][4];
            ldmA(a[0], Qh, wm * 32,      kc * 16, lane);
            ldmA(a[1], Qh, wm * 32 + 16, kc * 16, lane);
#pragma unroll
            for (int nt = 0; nt < 4; nt++)
                ldmB2(bfr[nt], Kb_s, wn * 64 + nt * 16, kc * 16, lane);
#pragma unroll
            for (int mi = 0; mi < 2; mi++)
#pragma unroll
                for (int ni = 0; ni < 8; ni++)
                    mma_f16(acc[mi][ni], a[mi], &bfr[ni >> 1][(ni & 1) * 2]);
        }

#pragma unroll
        for (int mi = 0; mi < 2; mi++)
#pragma unroll
            for (int ni = 0; ni < 8; ni++) {
                rs[mi][0] += fexp2(acc[mi][ni][0]) + fexp2(acc[mi][ni][1]);
                rs[mi][1] += fexp2(acc[mi][ni][2]) + fexp2(acc[mi][ni][3]);
            }
    }

#pragma unroll
    for (int mi = 0; mi < 2; mi++)
#pragma unroll
        for (int hf = 0; hf < 2; hf++) {
            float v = rs[mi][hf];
            v += __shfl_xor_sync(0xFFFFFFFFu, v, 1);
            v += __shfl_xor_sync(0xFFFFFFFFu, v, 2);
            rs[mi][hf] = v;
        }
    if (lc == 0) {
#pragma unroll
        for (int mi = 0; mi < 2; mi++)
#pragma unroll
            for (int hf = 0; hf < 2; hf++)
                red[(wm * 32 + mi * 16 + hf * 8 + lr) * 2 + wn] = rs[mi][hf];
    }
    __syncthreads();
    if (t < 128)
        rowsum_out[(size_t)bh * SQ + q0 + t] = red[t * 2 + 0] + red[t * 2 + 1];
}

// ============================================================================
// Flash pass 1: recompute S, P = exp2*inv; write attn fp32; O += P@V via
// register-fragment reuse. 3-stage cp.async K,V pipeline. kv tile 64.
// ============================================================================
__global__ __launch_bounds__(256, 2) void flash1_kernel(
    const __half* __restrict__ qh, const __half* __restrict__ kh,
    const __half* __restrict__ vh, const float* __restrict__ rowsum_in,
    float* __restrict__ attn, __half* __restrict__ ctxh)
{
    extern __shared__ char smc[];
    __half* Qh  = (__half*)smc;                        // 18432
    __half* Kh  = (__half*)(smc + 18432);              // 3 x 9216 = 27648
    __half* Vh  = (__half*)(smc + 18432 + 27648);      // 3 x 9216 = 27648
    float*  inv = (float*)(smc + 18432 + 55296);       // 512
    float* stageO = (float*)(smc + 18432);             // overlay on Kh/Vh

    const int bh = blockIdx.y;
    const int b  = bh >> 3;
    const int h  = bh & 7;
    const int q0 = blockIdx.x * 128;

    const int t    = threadIdx.x;
    const int lane = t & 31;
    const int warp = t >> 5;
    const int wm   = warp >> 1;
    const int wn   = warp & 1;
    const int lr   = lane >> 2;
    const int lc   = lane & 3;

    const __half* Qb = qh + (size_t)b * SQ * DD + h * HDIM;
    const __half* Kb = kh + (size_t)b * SK * DD + h * HDIM;
    const __half* Vb = vh + (size_t)b * SK * DD + h * HDIM;
    const uint32_t kh0 = sptr(Kh);
    const uint32_t vh0 = sptr(Vh);

#pragma unroll
    for (int i = 0; i < 8; i++) {
        int s = t + 256 * i, r = s >> 4, c4 = (s & 15) * 4;
        *(uint2*)&Qh[r * PS + c4] = *(const uint2*)&Qb[(size_t)(q0 + r) * DD + c4];
    }
    if (t < 128)
        inv[t] = 1.0f / rowsum_in[(size_t)bh * SQ + q0 + t];

    // prologue: issue K,V tiles 0, 1
#pragma unroll
    for (int pc = 0; pc < 2; pc++) {
#pragma unroll
        for (int i = 0; i < 2; i++) {
            int s = t + 256 * i, r = s >> 3, c8 = (s & 7) * 8;
            cp16(kh0 + (pc * 64 * PS + r * PS + c8) * 2,
                 &Kb[(size_t)(pc * 64 + r) * DD + c8]);
            cp16(vh0 + (pc * 64 * PS + r * PS + c8) * 2,
                 &Vb[(size_t)(pc * 64 + r) * DD + c8]);
        }
        CP_COMMIT();
    }

    const int T = SK / 64;
    float oacc[2][8][4] = {};
    float* arow = attn + ((size_t)bh * SQ + q0) * SK;

    for (int it = 0; it < T; it++) {
        int kv0 = it * 64;
        __syncthreads();
        if (it + 2 < T) {
            int kv = kv0 + 128;
            int nb = (it + 2) % 3;
#pragma unroll
            for (int i = 0; i < 2; i++) {
                int s = t + 256 * i, r = s >> 3, c8 = (s & 7) * 8;
                cp16(kh0 + (nb * 64 * PS + r * PS + c8) * 2, &Kb[(size_t)(kv + r) * DD + c8]);
                cp16(vh0 + (nb * 64 * PS + r * PS + c8) * 2, &Vb[(size_t)(kv + r) * DD + c8]);
            }
            CP_COMMIT();
            CP_WAIT2();
        } else if (it + 1 < T) {
            CP_WAIT1();
        } else {
            CP_WAIT0();
        }
        __syncthreads();

        const __half* Kb_s = Kh + (it % 3) * 64 * PS;
        const __half* Vb_s = Vh + (it % 3) * 64 * PS;

        // GEMM1: S(128x64) = Q @ K^T  (warp: 32 q x 32 kv)
        float acc[2][4][4] = {};
#pragma unroll
        for (int kc = 0; kc < 4; kc++) {
            uint32_t a[2][4], bfr[2][4];
            ldmA(a[0], Qh, wm * 32,      kc * 16, lane);
            ldmA(a[1], Qh, wm * 32 + 16, kc * 16, lane);
            ldmB2(bfr[0], Kb_s, wn * 32,      kc * 16, lane);
            ldmB2(bfr[1], Kb_s, wn * 32 + 16, kc * 16, lane);
#pragma unroll
            for (int mi = 0; mi < 2; mi++)
#pragma unroll
                for (int ni = 0; ni < 4; ni++)
                    mma_f16(acc[mi][ni], a[mi], &bfr[ni >> 1][(ni & 1) * 2]);
        }

        // exp2 * inv: write attn (fp32) + pack P directly into A-fragments
        uint32_t pa[2][2][4];
#pragma unroll
        for (int mi = 0; mi < 2; mi++) {
            int r = wm * 32 + mi * 16 + lr;
            float iv0 = inv[r], iv1 = inv[r + 8];
#pragma unroll
            for (int ni = 0; ni < 4; ni++) {
                int c = wn * 32 + ni * 8 + lc * 2;
                float e0 = fexp2(acc[mi][ni][0]) * iv0;
                float e1 = fexp2(acc[mi][ni][1]) * iv0;
                float e2 = fexp2(acc[mi][ni][2]) * iv1;
                float e3 = fexp2(acc[mi][ni][3]) * iv1;
                *(float2*)&arow[(size_t)r * SK + kv0 + c]       = make_float2(e0, e1);
                *(float2*)&arow[(size_t)(r + 8) * SK + kv0 + c] = make_float2(e2, e3);
                pa[mi][ni >> 1][(ni & 1) * 2 + 0] = packh2(e0, e1);
                pa[mi][ni >> 1][(ni & 1) * 2 + 1] = packh2(e2, e3);
            }
        }

        // GEMM2: O_partial += P(32q x 32kv) @ V(32kv x 64d)
#pragma unroll
        for (int pair = 0; pair < 2; pair++) {
            int kk = wn * 32 + pair * 16;
            uint32_t bfr[4][4];
#pragma unroll
            for (int nq = 0; nq < 4; nq++)
                ldmBt2(bfr[nq], Vb_s, kk, nq * 16, lane);
#pragma unroll
            for (int mi = 0; mi < 2; mi++)
#pragma unroll
                for (int nt = 0; nt < 8; nt++)
                    mma_f16(oacc[mi][nt], pa[mi][pair], &bfr[nt >> 1][(nt & 1) * 2]);
        }
    }

    // Reduce O across the wn pair via smem, store ctxh
    __syncthreads();
    if (wn == 1) {
#pragma unroll
        for (int mi = 0; mi < 2; mi++)
#pragma unroll
            for (int nt = 0; nt < 8; nt++) {
                int r = wm * 32 + mi * 16 + lr;
                int c = nt * 8 + lc * 2;
                stageO[r * SP + c]           = oacc[mi][nt][0];
                stageO[r * SP + c + 1]       = oacc[mi][nt][1];
                stageO[(r + 8) * SP + c]     = oacc[mi][nt][2];
                stageO[(r + 8) * SP + c + 1] = oacc[mi][nt][3];
            }
    }
    __syncthreads();
    if (wn == 0) {
#pragma unroll
        for (int mi = 0; mi < 2; mi++) {
            size_t r0 = (size_t)b * SQ + q0 + wm * 32 + mi * 16 + lr;
            int rs = wm * 32 + mi * 16 + lr;
#pragma unroll
            for (int nt = 0; nt < 8; nt++) {
                int c = nt * 8 + lc * 2;
                float o0 = oacc[mi][nt][0] + stageO[rs * SP + c];
                float o1 = oacc[mi][nt][1] + stageO[rs * SP + c + 1];
                float o2 = oacc[mi][nt][2] + stageO[(rs + 8) * SP + c];
                float o3 = oacc[mi][nt][3] + stageO[(rs + 8) * SP + c + 1];
                int cg = h * HDIM + c;
                *(half2*)&ctxh[r0 * DD + cg]       = __floats2half2_rn(o0, o1);
                *(half2*)&ctxh[(r0 + 8) * DD + cg] = __floats2half2_rn(o2, o3);
            }
        }
    }
}

// ============================================================================
// LayerNorm: warp-per-row, shuffle-only
// ============================================================================
__global__ __launch_bounds__(256) void ln_kernel(
    float* __restrict__ out, const float* __restrict__ g,
    const float* __restrict__ bta)
{
    const int warp = threadIdx.x >> 5;
    const int lane = threadIdx.x & 31;
    const size_t row = (size_t)blockIdx.x * 8 + warp;
    float* p = out + row * DD;

    float4 v[4];
    float sum = 0.f;
#pragma unroll
    for (int j = 0; j < 4; j++) {
        v[j] = *(const float4*)&p[lane * 4 + j * 128];
        sum += (v[j].x + v[j].y) + (v[j].z + v[j].w);
    }
#pragma unroll
    for (int o = 16; o; o >>= 1) sum += __shfl_xor_sync(0xFFFFFFFFu, sum, o);
    float mu = sum * (1.0f / DD);

    float var = 0.f;
#pragma unroll
    for (int j = 0; j < 4; j++) {
        float dx = v[j].x - mu, dy = v[j].y - mu, dz = v[j].z - mu, dw = v[j].w - mu;
        var += dx * dx + dy * dy + dz * dz + dw * dw;
    }
#pragma unroll
    for (int o = 16; o; o >>= 1) var += __shfl_xor_sync(0xFFFFFFFFu, var, o);
    float rstd = rsqrtf(var * (1.0f / DD) + LNEPS);

#pragma unroll
    for (int j = 0; j < 4; j++) {
        float4 gg = *(const float4*)&g[lane * 4 + j * 128];
        float4 bb = *(const float4*)&bta[lane * 4 + j * 128];
        float4 o;
        o.x = (v[j].x - mu) * rstd * gg.x + bb.x;
        o.y = (v[j].y - mu) * rstd * gg.y + bb.y;
        o.z = (v[j].z - mu) * rstd * gg.z + bb.z;
        o.w = (v[j].w - mu) * rstd * gg.w + bb.w;
        *(float4*)&p[lane * 4 + j * 128] = o;
    }
}

// ============================================================================
// Launch
// ============================================================================
#define SMEM_LIN (128 * SPL * 4)                                  /* 67584 (stage) > 4x18432=73728 -> use 73728 */
#define SMEM_LIN_TOT (2 * 128 * PS * 2 + 2 * 128 * PS * 2)        /* 73728 */
#define SMEM_F0  (128 * PS * 2 + 2 * 128 * PS * 2 + 1024)         /* 56320 */
#define SMEM_F1  (18432 + 27648 + 27648 + 512)                    /* 74240 */

extern "C" void kernel_launch(void* const* d_in, const int* in_sizes, int n_in,
                              void* d_out, int out_size)
{
    const float* q   = (const float*)d_in[0];
    const float* k   = (const float*)d_in[1];
    const float* v   = (const float*)d_in[2];
    const float* Wq  = (const float*)d_in[3];
    const float* bq  = (const float*)d_in[4];
    const float* Wk  = (const float*)d_in[5];
    const float* bk  = (const float*)d_in[6];
    const float* Wv  = (const float*)d_in[7];
    const float* bv  = (const float*)d_in[8];
    const float* Wo  = (const float*)d_in[9];
    const float* bo  = (const float*)d_in[10];
    const float* lng = (const float*)d_in[11];
    const float* lnb = (const float*)d_in[12];

    float* out = (float*)d_out;

    float *qlin, *attn_scr, *rowsum;
    __half *qh, *kh, *vh, *ctxh, *inqh, *inkh, *invh, *Wqh, *Wkh, *Wvh, *Woh;
    cudaGetSymbolAddress((void**)&qlin, g_qlin);
    cudaGetSymbolAddress((void**)&attn_scr, g_attn_scratch);
    cudaGetSymbolAddress((void**)&rowsum, g_rowsum);
    cudaGetSymbolAddress((void**)&qh, g_qh);
    cudaGetSymbolAddress((void**)&kh, g_kh);
    cudaGetSymbolAddress((void**)&vh, g_vh);
    cudaGetSymbolAddress((void**)&ctxh, g_ctxh);
    cudaGetSymbolAddress((void**)&inqh, g_inqh);
    cudaGetSymbolAddress((void**)&inkh, g_inkh);
    cudaGetSymbolAddress((void**)&invh, g_invh);
    cudaGetSymbolAddress((void**)&Wqh, g_Wqh);
    cudaGetSymbolAddress((void**)&Wkh, g_Wkh);
    cudaGetSymbolAddress((void**)&Wvh, g_Wvh);
    cudaGetSymbolAddress((void**)&Woh, g_Woh);

    float* attn = ((size_t)out_size >= OUT_ELEMS + ATTN_ELEMS)
                      ? out + OUT_ELEMS : attn_scr;

    cudaFuncSetAttribute((const void*)linear_kernel<false, true, true>,
                         cudaFuncAttributeMaxDynamicSharedMemorySize, SMEM_LIN_TOT);
    cudaFuncSetAttribute((const void*)linear_kernel<false, false, true>,
                         cudaFuncAttributeMaxDynamicSharedMemorySize, SMEM_LIN_TOT);
    cudaFuncSetAttribute((const void*)linear_kernel<true, true, false>,
                         cudaFuncAttributeMaxDynamicSharedMemorySize, SMEM_LIN_TOT);
    cudaFuncSetAttribute((const void*)flash0_kernel,
                         cudaFuncAttributeMaxDynamicSharedMemorySize, SMEM_F0);
    cudaFuncSetAttribute((const void*)flash1_kernel,
                         cudaFuncAttributeMaxDynamicSharedMemorySize, SMEM_F1);

    dim3 blk(256);

    // 0) fp16 conversions (2 launches)
    const int NIN4 = (BB * SQ * DD) / 4;
    const int NW4  = (DD * DD) / 4;
    to_half3_kernel<<<dim3((NIN4 + 255) / 256, 3), blk>>>(q, k, v, inqh, inkh, invh, NIN4);
    to_half4_kernel<<<dim3((NW4 + 255) / 256, 4), blk>>>(Wq, Wk, Wv, Wo,
                                                         Wqh, Wkh, Wvh, Woh, NW4);

    // 1) projections (CTA 128x128)
    dim3 gLin(DD / 128, (BB * SQ) / 128);
    linear_kernel<false, true, true><<<gLin, blk, SMEM_LIN_TOT>>>(
        inqh, Wqh, bq, nullptr, qlin, qh, FSCALE * LOG2E);
    linear_kernel<false, false, true><<<gLin, blk, SMEM_LIN_TOT>>>(
        inkh, Wkh, bk, nullptr, nullptr, kh, 1.0f);
    linear_kernel<false, false, true><<<gLin, blk, SMEM_LIN_TOT>>>(
        invh, Wvh, bv, nullptr, nullptr, vh, 1.0f);

    // 2) pass A: row sums (kv tile 128)
    dim3 gFl(SQ / 128, BB * HH);
    flash0_kernel<<<gFl, blk, SMEM_F0>>>(qh, kh, rowsum);

    // 3) pass B: normalized attn + O = P@V (register-fragment reuse)
    flash1_kernel<<<gFl, blk, SMEM_F1>>>(qh, kh, vh, rowsum, attn, ctxh);

    // 4) output projection + residual(q_lin)
    linear_kernel<true, true, false><<<gLin, blk, SMEM_LIN_TOT>>>(
        ctxh, Woh, bo, qlin, out, nullptr, 1.0f);

    // 5) layernorm (warp per row)
    ln_kernel<<<(BB * SQ) / 8, blk>>>(out, lng, lnb);
}

// round 16
// speedup vs baseline: 1.1458x; 1.0161x over previous
#include <cuda_runtime.h>
#include <cuda_fp16.h>
#include <math.h>
#include <stdint.h>

#define BB 4
#define SQ 2048
#define SK 2048
#define DD 512
#define HH 8
#define HDIM 64
#define FSCALE 0.125f
#define LOG2E 1.44269504088896f
#define LNEPS 1e-5f

#define OUT_ELEMS ((size_t)BB * SQ * DD)
#define ATTN_ELEMS ((size_t)BB * HH * SQ * (size_t)SK)

#define PS 72     /* smem half-tile row stride (halves): 144B rows */
#define SP 68     /* fp32 staging stride (floats), <=64 cols */
#define SPL 132   /* fp32 staging stride for 128-col epilogue */

// ---- scratch ----
__device__ float  g_qlin[BB * SQ * DD];
__device__ __half g_qh[BB * SQ * DD];
__device__ __half g_kh[BB * SK * DD];
__device__ __half g_vh[BB * SK * DD];
__device__ __half g_ctxh[BB * SQ * DD];
__device__ __half g_inqh[BB * SQ * DD];
__device__ __half g_inkh[BB * SK * DD];
__device__ __half g_invh[BB * SK * DD];
__device__ __half g_Wqh[DD * DD];
__device__ __half g_Wkh[DD * DD];
__device__ __half g_Wvh[DD * DD];
__device__ __half g_Woh[DD * DD];
__device__ float  g_rowsum[(size_t)BB * HH * SQ];
__device__ float  g_attn_scratch[ATTN_ELEMS];

// ---- helpers ----
__device__ __forceinline__ uint32_t sptr(const void* p) {
    return (uint32_t)__cvta_generic_to_shared(p);
}
__device__ __forceinline__ void cp16(uint32_t dst, const void* src) {
    asm volatile("cp.async.ca.shared.global [%0], [%1], 16;" :: "r"(dst), "l"(src));
}
#define CP_COMMIT() asm volatile("cp.async.commit_group;")
#define CP_WAIT2()  asm volatile("cp.async.wait_group 2;")
#define CP_WAIT1()  asm volatile("cp.async.wait_group 1;")
#define CP_WAIT0()  asm volatile("cp.async.wait_group 0;")

__device__ __forceinline__ float fexp2(float x) {
    float y;
    asm("ex2.approx.f32 %0, %1;" : "=f"(y) : "f"(x));
    return y;
}
__device__ __forceinline__ uint32_t packh2(float a, float b) {
    half2 h = __floats2half2_rn(a, b);
    return *(uint32_t*)&h;
}

__device__ __forceinline__ void mma_f16(float* c, const uint32_t* a, const uint32_t* b) {
    asm volatile(
        "mma.sync.aligned.m16n8k16.row.col.f32.f16.f16.f32 "
        "{%0,%1,%2,%3}, {%4,%5,%6,%7}, {%8,%9}, {%0,%1,%2,%3};"
        : "+f"(c[0]), "+f"(c[1]), "+f"(c[2]), "+f"(c[3])
        : "r"(a[0]), "r"(a[1]), "r"(a[2]), "r"(a[3]), "r"(b[0]), "r"(b[1]));
}

__device__ __forceinline__ void ldmA(uint32_t* a, const __half* base, int row0, int k0, int lane) {
    const __half* p = base + (size_t)(row0 + (lane & 7) + ((lane >> 3) & 1) * 8) * PS
                      + k0 + (lane >> 4) * 8;
    asm volatile("ldmatrix.sync.aligned.m8n8.x4.shared.b16 {%0,%1,%2,%3}, [%4];"
                 : "=r"(a[0]), "=r"(a[1]), "=r"(a[2]), "=r"(a[3]) : "r"(sptr(p)));
}
__device__ __forceinline__ void ldmB2(uint32_t* b, const __half* base, int n0, int k0, int lane) {
    const __half* p = base + (size_t)(n0 + (lane & 7) + (lane >> 4) * 8) * PS
                      + k0 + ((lane >> 3) & 1) * 8;
    asm volatile("ldmatrix.sync.aligned.m8n8.x4.shared.b16 {%0,%1,%2,%3}, [%4];"
                 : "=r"(b[0]), "=r"(b[1]), "=r"(b[2]), "=r"(b[3]) : "r"(sptr(p)));
}
__device__ __forceinline__ void ldmBt2(uint32_t* b, const __half* base, int k0, int n0, int lane) {
    const __half* p = base + (size_t)(k0 + (lane & 7) + ((lane >> 3) & 1) * 8) * PS
                      + n0 + (lane >> 4) * 8;
    asm volatile("ldmatrix.sync.aligned.m8n8.x4.trans.shared.b16 {%0,%1,%2,%3}, [%4];"
                 : "=r"(b[0]), "=r"(b[1]), "=r"(b[2]), "=r"(b[3]) : "r"(sptr(p)));
}

// ============================================================================
// fp32 -> fp16 conversions, merged launches
// ============================================================================
__global__ __launch_bounds__(256) void to_half3_kernel(
    const float* __restrict__ s0, const float* __restrict__ s1,
    const float* __restrict__ s2,
    __half* __restrict__ d0, __half* __restrict__ d1, __half* __restrict__ d2,
    int n4)
{
    const float* s = blockIdx.y == 0 ? s0 : blockIdx.y == 1 ? s1 : s2;
    __half*      d = blockIdx.y == 0 ? d0 : blockIdx.y == 1 ? d1 : d2;
    int i = blockIdx.x * 256 + threadIdx.x;
    if (i < n4) {
        float4 v = ((const float4*)s)[i];
        ((half2*)d)[i * 2]     = __floats2half2_rn(v.x, v.y);
        ((half2*)d)[i * 2 + 1] = __floats2half2_rn(v.z, v.w);
    }
}
__global__ __launch_bounds__(256) void to_half4_kernel(
    const float* __restrict__ s0, const float* __restrict__ s1,
    const float* __restrict__ s2, const float* __restrict__ s3,
    __half* __restrict__ d0, __half* __restrict__ d1,
    __half* __restrict__ d2, __half* __restrict__ d3, int n4)
{
    const float* s = blockIdx.y == 0 ? s0 : blockIdx.y == 1 ? s1
                   : blockIdx.y == 2 ? s2 : s3;
    __half*      d = blockIdx.y == 0 ? d0 : blockIdx.y == 1 ? d1
                   : blockIdx.y == 2 ? d2 : d3;
    int i = blockIdx.x * 256 + threadIdx.x;
    if (i < n4) {
        float4 v = ((const float4*)s)[i];
        ((half2*)d)[i * 2]     = __floats2half2_rn(v.x, v.y);
        ((half2*)d)[i * 2 + 1] = __floats2half2_rn(v.z, v.w);
    }
}

// ============================================================================
// Shared linear mainloop body (CTA 128x128, k-chunks 64, 2-stage cp.async,
// 8 warps, warp 32x64), used by both qkv_kernel and outproj.
// ============================================================================
template <bool ADD_RES, bool WRITE_F, bool WRITE_H>
__device__ __forceinline__ void linear_body(
    const __half* __restrict__ A, const __half* __restrict__ W,
    const float* __restrict__ bias, const float* __restrict__ res,
    float* __restrict__ C, __half* __restrict__ Ch, float hscale,
    int row0, int col0, char* smc)
{
    __half* Ah = (__half*)smc;                       // 2 x [128][PS] = 36864 B
    __half* Wh = (__half*)(smc + 2 * 128 * PS * 2);  // 2 x [128][PS] = 36864 B
    float* stage = (float*)smc;                      // overlay [128][SPL]

    const int t    = threadIdx.x;
    const int lane = t & 31;
    const int warp = t >> 5;
    const int wm   = warp >> 1;
    const int wn   = warp & 1;
    const int lr   = lane >> 2;
    const int lc   = lane & 3;

    const uint32_t ah0 = sptr(Ah);
    const uint32_t wh0 = sptr(Wh);

    // issue chunk 0
    {
#pragma unroll
        for (int i = 0; i < 4; i++) {
            int s = t + 256 * i, r = s >> 3, c8 = (s & 7) * 8;
            cp16(ah0 + (r * PS + c8) * 2, &A[(size_t)(row0 + r) * DD + c8]);
            cp16(wh0 + (r * PS + c8) * 2, &W[(size_t)(col0 + r) * DD + c8]);
        }
        CP_COMMIT();
    }

    float acc[2][8][4] = {};

    for (int kc0 = 0; kc0 < 8; kc0++) {
        __syncthreads();
        if (kc0 + 1 < 8) {
            int k0 = (kc0 + 1) * 64;
            int nb = (kc0 + 1) & 1;
#pragma unroll
            for (int i = 0; i < 4; i++) {
                int s = t + 256 * i, r = s >> 3, c8 = (s & 7) * 8;
                cp16(ah0 + (nb * 128 * PS + r * PS + c8) * 2,
                     &A[(size_t)(row0 + r) * DD + k0 + c8]);
                cp16(wh0 + (nb * 128 * PS + r * PS + c8) * 2,
                     &W[(size_t)(col0 + r) * DD + k0 + c8]);
            }
            CP_COMMIT();
            CP_WAIT1();
        } else {
            CP_WAIT0();
        }
        __syncthreads();

        const __half* Ab = Ah + (kc0 & 1) * 128 * PS;
        const __half* Wb = Wh + (kc0 & 1) * 128 * PS;
#pragma unroll
        for (int kc = 0; kc < 4; kc++) {
            uint32_t a[2][4], bfr[4][4];
            ldmA(a[0], Ab, wm * 32,      kc * 16, lane);
            ldmA(a[1], Ab, wm * 32 + 16, kc * 16, lane);
#pragma unroll
            for (int nt = 0; nt < 4; nt++)
                ldmB2(bfr[nt], Wb, wn * 64 + nt * 16, kc * 16, lane);
#pragma unroll
            for (int mi = 0; mi < 2; mi++)
#pragma unroll
                for (int ni = 0; ni < 8; ni++)
                    mma_f16(acc[mi][ni], a[mi], &bfr[ni >> 1][(ni & 1) * 2]);
        }
    }

    // bias
#pragma unroll
    for (int ni = 0; ni < 8; ni++) {
        int c = col0 + wn * 64 + ni * 8 + lc * 2;
        float b0 = bias[c], b1 = bias[c + 1];
#pragma unroll
        for (int mi = 0; mi < 2; mi++) {
            acc[mi][ni][0] += b0; acc[mi][ni][1] += b1;
            acc[mi][ni][2] += b0; acc[mi][ni][3] += b1;
        }
    }

    // stage + coalesced store
    __syncthreads();
#pragma unroll
    for (int mi = 0; mi < 2; mi++)
#pragma unroll
        for (int ni = 0; ni < 8; ni++) {
            int r = wm * 32 + mi * 16 + lr;
            int c = wn * 64 + ni * 8 + lc * 2;
            stage[r * SPL + c]           = acc[mi][ni][0];
            stage[r * SPL + c + 1]       = acc[mi][ni][1];
            stage[(r + 8) * SPL + c]     = acc[mi][ni][2];
            stage[(r + 8) * SPL + c + 1] = acc[mi][ni][3];
        }
    __syncthreads();
#pragma unroll
    for (int i = 0; i < 16; i++) {
        int s = t + 256 * i, r = s >> 5, c4 = (s & 31) * 4;
        float4 v = *(float4*)&stage[r * SPL + c4];
        size_t g = (size_t)(row0 + r) * DD + col0 + c4;
        if (ADD_RES) {
            float4 rr = *(const float4*)&res[g];
            v.x += rr.x; v.y += rr.y; v.z += rr.z; v.w += rr.w;
        }
        if (WRITE_F) *(float4*)&C[g] = v;
        if (WRITE_H) {
            *(half2*)&Ch[g]     = __floats2half2_rn(v.x * hscale, v.y * hscale);
            *(half2*)&Ch[g + 2] = __floats2half2_rn(v.z * hscale, v.w * hscale);
        }
    }
}

// ============================================================================
// Merged QKV projection: blockIdx.z selects which projection.
// z==0: qlin (fp32) + qh (half, scaled); z==1: kh; z==2: vh.
// ============================================================================
__global__ __launch_bounds__(256, 2) void qkv_kernel(
    const __half* __restrict__ inq, const __half* __restrict__ ink,
    const __half* __restrict__ invv,
    const __half* __restrict__ Wqh, const __half* __restrict__ Wkh,
    const __half* __restrict__ Wvh,
    const float* __restrict__ bq, const float* __restrict__ bk,
    const float* __restrict__ bv,
    float* __restrict__ qlin, __half* __restrict__ qh,
    __half* __restrict__ kh, __half* __restrict__ vh)
{
    extern __shared__ char smc[];
    const int z = blockIdx.z;
    const int row0 = blockIdx.y * 128;
    const int col0 = blockIdx.x * 128;

    if (z == 0) {
        linear_body<false, true, true>(inq, Wqh, bq, nullptr, qlin, qh,
                                       FSCALE * LOG2E, row0, col0, smc);
    } else if (z == 1) {
        linear_body<false, false, true>(ink, Wkh, bk, nullptr, nullptr, kh,
                                        1.0f, row0, col0, smc);
    } else {
        linear_body<false, false, true>(invv, Wvh, bv, nullptr, nullptr, vh,
                                        1.0f, row0, col0, smc);
    }
}

// ============================================================================
// Out projection: fp32 out = ctxh@Wo^T + bo + res(qlin)
// ============================================================================
__global__ __launch_bounds__(256, 2) void outproj_kernel(
    const __half* __restrict__ A, const __half* __restrict__ W,
    const float* __restrict__ bias, const float* __restrict__ res,
    float* __restrict__ C)
{
    extern __shared__ char smc[];
    linear_body<true, true, false>(A, W, bias, res, C, nullptr, 1.0f,
                                   blockIdx.y * 128, blockIdx.x * 128, smc);
}

// ============================================================================
// Flash pass 0: rowsums of exp2(Qs@K^T). kv tiles of 128, 2-stage cp.async.
// CTA 128 q x kv 128. 8 warps (4m x 2n), warp 32q x 64kv.
// ============================================================================
__global__ __launch_bounds__(256, 2) void flash0_kernel(
    const __half* __restrict__ qh, const __half* __restrict__ kh,
    float* __restrict__ rowsum_out)
{
    extern __shared__ char smc[];
    __half* Qh = (__half*)smc;                      // [128][PS] = 18432
    __half* Kh = (__half*)(smc + 128 * PS * 2);     // 2 x [128][PS] = 36864
    float*  red = (float*)(smc + 128 * PS * 2 + 2 * 128 * PS * 2); // [128][2]

    const int bh = blockIdx.y;
    const int b  = bh >> 3;
    const int h  = bh & 7;
    const int q0 = blockIdx.x * 128;

    const int t    = threadIdx.x;
    const int lane = t & 31;
    const int warp = t >> 5;
    const int wm   = warp >> 1;
    const int wn   = warp & 1;
    const int lr   = lane >> 2;
    const int lc   = lane & 3;

    const __half* Qb = qh + (size_t)b * SQ * DD + h * HDIM;
    const __half* Kb = kh + (size_t)b * SK * DD + h * HDIM;
    const uint32_t kh0 = sptr(Kh);

    // Q tile (once)
#pragma unroll
    for (int i = 0; i < 8; i++) {
        int s = t + 256 * i, r = s >> 4, c4 = (s & 15) * 4;
        *(uint2*)&Qh[r * PS + c4] = *(const uint2*)&Qb[(size_t)(q0 + r) * DD + c4];
    }

    // issue K tile 0 (128 rows)
#pragma unroll
    for (int i = 0; i < 4; i++) {
        int s = t + 256 * i, r = s >> 3, c8 = (s & 7) * 8;
        cp16(kh0 + (r * PS + c8) * 2, &Kb[(size_t)r * DD + c8]);
    }
    CP_COMMIT();

    const int T = SK / 128;
    float rs[2][2] = {};

    for (int it = 0; it < T; it++) {
        __syncthreads();
        if (it + 1 < T) {
            int kv = (it + 1) * 128;
            int nb = (it + 1) & 1;
#pragma unroll
            for (int i = 0; i < 4; i++) {
                int s = t + 256 * i, r = s >> 3, c8 = (s & 7) * 8;
                cp16(kh0 + (nb * 128 * PS + r * PS + c8) * 2,
                     &Kb[(size_t)(kv + r) * DD + c8]);
            }
            CP_COMMIT();
            CP_WAIT1();
        } else {
            CP_WAIT0();
        }
        __syncthreads();

        const __half* Kb_s = Kh + (it & 1) * 128 * PS;
        float acc[2][8][4] = {};
#pragma unroll
        for (int kc = 0; kc < 4; kc++) {
            uint32_t a[2][4], bfr[4][4];
            ldmA(a[0], Qh, wm * 32,      kc * 16, lane);
            ldmA(a[1], Qh, wm * 32 + 16, kc * 16, lane);
#pragma unroll
            for (int nt = 0; nt < 4; nt++)
                ldmB2(bfr[nt], Kb_s, wn * 64 + nt * 16, kc * 16, lane);
#pragma unroll
            for (int mi = 0; mi < 2; mi++)
#pragma unroll
                for (int ni = 0; ni < 8; ni++)
                    mma_f16(acc[mi][ni], a[mi], &bfr[ni >> 1][(ni & 1) * 2]);
        }

#pragma unroll
        for (int mi = 0; mi < 2; mi++)
#pragma unroll
            for (int ni = 0; ni < 8; ni++) {
                rs[mi][0] += fexp2(acc[mi][ni][0]) + fexp2(acc[mi][ni][1]);
                rs[mi][1] += fexp2(acc[mi][ni][2]) + fexp2(acc[mi][ni][3]);
            }
    }

#pragma unroll
    for (int mi = 0; mi < 2; mi++)
#pragma unroll
        for (int hf = 0; hf < 2; hf++) {
            float v = rs[mi][hf];
            v += __shfl_xor_sync(0xFFFFFFFFu, v, 1);
            v += __shfl_xor_sync(0xFFFFFFFFu, v, 2);
            rs[mi][hf] = v;
        }
    if (lc == 0) {
#pragma unroll
        for (int mi = 0; mi < 2; mi++)
#pragma unroll
            for (int hf = 0; hf < 2; hf++)
                red[(wm * 32 + mi * 16 + hf * 8 + lr) * 2 + wn] = rs[mi][hf];
    }
    __syncthreads();
    if (t < 128)
        rowsum_out[(size_t)bh * SQ + q0 + t] = red[t * 2 + 0] + red[t * 2 + 1];
}

// ============================================================================
// Flash pass 1: recompute S, P = exp2*inv; write attn fp32; O += P@V via
// register-fragment reuse. 3-stage cp.async K,V pipeline. kv tile 64.
// ============================================================================
__global__ __launch_bounds__(256, 2) void flash1_kernel(
    const __half* __restrict__ qh, const __half* __restrict__ kh,
    const __half* __restrict__ vh, const float* __restrict__ rowsum_in,
    float* __restrict__ attn, __half* __restrict__ ctxh)
{
    extern __shared__ char smc[];
    __half* Qh  = (__half*)smc;                        // 18432
    __half* Kh  = (__half*)(smc + 18432);              // 3 x 9216 = 27648
    __half* Vh  = (__half*)(smc + 18432 + 27648);      // 3 x 9216 = 27648
    float*  inv = (float*)(smc + 18432 + 55296);       // 512
    float* stageO = (float*)(smc + 18432);             // overlay on Kh/Vh

    const int bh = blockIdx.y;
    const int b  = bh >> 3;
    const int h  = bh & 7;
    const int q0 = blockIdx.x * 128;

    const int t    = threadIdx.x;
    const int lane = t & 31;
    const int warp = t >> 5;
    const int wm   = warp >> 1;
    const int wn   = warp & 1;
    const int lr   = lane >> 2;
    const int lc   = lane & 3;

    const __half* Qb = qh + (size_t)b * SQ * DD + h * HDIM;
    const __half* Kb = kh + (size_t)b * SK * DD + h * HDIM;
    const __half* Vb = vh + (size_t)b * SK * DD + h * HDIM;
    const uint32_t kh0 = sptr(Kh);
    const uint32_t vh0 = sptr(Vh);

#pragma unroll
    for (int i = 0; i < 8; i++) {
        int s = t + 256 * i, r = s >> 4, c4 = (s & 15) * 4;
        *(uint2*)&Qh[r * PS + c4] = *(const uint2*)&Qb[(size_t)(q0 + r) * DD + c4];
    }
    if (t < 128)
        inv[t] = 1.0f / rowsum_in[(size_t)bh * SQ + q0 + t];

    // prologue: issue K,V tiles 0, 1
#pragma unroll
    for (int pc = 0; pc < 2; pc++) {
#pragma unroll
        for (int i = 0; i < 2; i++) {
            int s = t + 256 * i, r = s >> 3, c8 = (s & 7) * 8;
            cp16(kh0 + (pc * 64 * PS + r * PS + c8) * 2,
                 &Kb[(size_t)(pc * 64 + r) * DD + c8]);
            cp16(vh0 + (pc * 64 * PS + r * PS + c8) * 2,
                 &Vb[(size_t)(pc * 64 + r) * DD + c8]);
        }
        CP_COMMIT();
    }

    const int T = SK / 64;
    float oacc[2][8][4] = {};
    float* arow = attn + ((size_t)bh * SQ + q0) * SK;

    for (int it = 0; it < T; it++) {
        int kv0 = it * 64;
        __syncthreads();
        if (it + 2 < T) {
            int kv = kv0 + 128;
            int nb = (it + 2) % 3;
#pragma unroll
            for (int i = 0; i < 2; i++) {
                int s = t + 256 * i, r = s >> 3, c8 = (s & 7) * 8;
                cp16(kh0 + (nb * 64 * PS + r * PS + c8) * 2, &Kb[(size_t)(kv + r) * DD + c8]);
                cp16(vh0 + (nb * 64 * PS + r * PS + c8) * 2, &Vb[(size_t)(kv + r) * DD + c8]);
            }
            CP_COMMIT();
            CP_WAIT2();
        } else if (it + 1 < T) {
            CP_WAIT1();
        } else {
            CP_WAIT0();
        }
        __syncthreads();

        const __half* Kb_s = Kh + (it % 3) * 64 * PS;
        const __half* Vb_s = Vh + (it % 3) * 64 * PS;

        // GEMM1: S(128x64) = Q @ K^T  (warp: 32 q x 32 kv)
        float acc[2][4][4] = {};
#pragma unroll
        for (int kc = 0; kc < 4; kc++) {
            uint32_t a[2][4], bfr[2][4];
            ldmA(a[0], Qh, wm * 32,      kc * 16, lane);
            ldmA(a[1], Qh, wm * 32 + 16, kc * 16, lane);
            ldmB2(bfr[0], Kb_s, wn * 32,      kc * 16, lane);
            ldmB2(bfr[1], Kb_s, wn * 32 + 16, kc * 16, lane);
#pragma unroll
            for (int mi = 0; mi < 2; mi++)
#pragma unroll
                for (int ni = 0; ni < 4; ni++)
                    mma_f16(acc[mi][ni], a[mi], &bfr[ni >> 1][(ni & 1) * 2]);
        }

        // exp2 * inv: write attn (fp32) + pack P directly into A-fragments
        uint32_t pa[2][2][4];
#pragma unroll
        for (int mi = 0; mi < 2; mi++) {
            int r = wm * 32 + mi * 16 + lr;
            float iv0 = inv[r], iv1 = inv[r + 8];
#pragma unroll
            for (int ni = 0; ni < 4; ni++) {
                int c = wn * 32 + ni * 8 + lc * 2;
                float e0 = fexp2(acc[mi][ni][0]) * iv0;
                float e1 = fexp2(acc[mi][ni][1]) * iv0;
                float e2 = fexp2(acc[mi][ni][2]) * iv1;
                float e3 = fexp2(acc[mi][ni][3]) * iv1;
                *(float2*)&arow[(size_t)r * SK + kv0 + c]       = make_float2(e0, e1);
                *(float2*)&arow[(size_t)(r + 8) * SK + kv0 + c] = make_float2(e2, e3);
                pa[mi][ni >> 1][(ni & 1) * 2 + 0] = packh2(e0, e1);
                pa[mi][ni >> 1][(ni & 1) * 2 + 1] = packh2(e2, e3);
            }
        }

        // GEMM2: O_partial += P(32q x 32kv) @ V(32kv x 64d)
#pragma unroll
        for (int pair = 0; pair < 2; pair++) {
            int kk = wn * 32 + pair * 16;
            uint32_t bfr[4][4];
#pragma unroll
            for (int nq = 0; nq < 4; nq++)
                ldmBt2(bfr[nq], Vb_s, kk, nq * 16, lane);
#pragma unroll
            for (int mi = 0; mi < 2; mi++)
#pragma unroll
                for (int nt = 0; nt < 8; nt++)
                    mma_f16(oacc[mi][nt], pa[mi][pair], &bfr[nt >> 1][(nt & 1) * 2]);
        }
    }

    // Reduce O across the wn pair via smem, store ctxh
    __syncthreads();
    if (wn == 1) {
#pragma unroll
        for (int mi = 0; mi < 2; mi++)
#pragma unroll
            for (int nt = 0; nt < 8; nt++) {
                int r = wm * 32 + mi * 16 + lr;
                int c = nt * 8 + lc * 2;
                stageO[r * SP + c]           = oacc[mi][nt][0];
                stageO[r * SP + c + 1]       = oacc[mi][nt][1];
                stageO[(r + 8) * SP + c]     = oacc[mi][nt][2];
                stageO[(r + 8) * SP + c + 1] = oacc[mi][nt][3];
            }
    }
    __syncthreads();
    if (wn == 0) {
#pragma unroll
        for (int mi = 0; mi < 2; mi++) {
            size_t r0 = (size_t)b * SQ + q0 + wm * 32 + mi * 16 + lr;
            int rs = wm * 32 + mi * 16 + lr;
#pragma unroll
            for (int nt = 0; nt < 8; nt++) {
                int c = nt * 8 + lc * 2;
                float o0 = oacc[mi][nt][0] + stageO[rs * SP + c];
                float o1 = oacc[mi][nt][1] + stageO[rs * SP + c + 1];
                float o2 = oacc[mi][nt][2] + stageO[(rs + 8) * SP + c];
                float o3 = oacc[mi][nt][3] + stageO[(rs + 8) * SP + c + 1];
                int cg = h * HDIM + c;
                *(half2*)&ctxh[r0 * DD + cg]       = __floats2half2_rn(o0, o1);
                *(half2*)&ctxh[(r0 + 8) * DD + cg] = __floats2half2_rn(o2, o3);
            }
        }
    }
}

// ============================================================================
// LayerNorm: warp-per-row, shuffle-only
// ============================================================================
__global__ __launch_bounds__(256) void ln_kernel(
    float* __restrict__ out, const float* __restrict__ g,
    const float* __restrict__ bta)
{
    const int warp = threadIdx.x >> 5;
    const int lane = threadIdx.x & 31;
    const size_t row = (size_t)blockIdx.x * 8 + warp;
    float* p = out + row * DD;

    float4 v[4];
    float sum = 0.f;
#pragma unroll
    for (int j = 0; j < 4; j++) {
        v[j] = *(const float4*)&p[lane * 4 + j * 128];
        sum += (v[j].x + v[j].y) + (v[j].z + v[j].w);
    }
#pragma unroll
    for (int o = 16; o; o >>= 1) sum += __shfl_xor_sync(0xFFFFFFFFu, sum, o);
    float mu = sum * (1.0f / DD);

    float var = 0.f;
#pragma unroll
    for (int j = 0; j < 4; j++) {
        float dx = v[j].x - mu, dy = v[j].y - mu, dz = v[j].z - mu, dw = v[j].w - mu;
        var += dx * dx + dy * dy + dz * dz + dw * dw;
    }
#pragma unroll
    for (int o = 16; o; o >>= 1) var += __shfl_xor_sync(0xFFFFFFFFu, var, o);
    float rstd = rsqrtf(var * (1.0f / DD) + LNEPS);

#pragma unroll
    for (int j = 0; j < 4; j++) {
        float4 gg = *(const float4*)&g[lane * 4 + j * 128];
        float4 bb = *(const float4*)&bta[lane * 4 + j * 128];
        float4 o;
        o.x = (v[j].x - mu) * rstd * gg.x + bb.x;
        o.y = (v[j].y - mu) * rstd * gg.y + bb.y;
        o.z = (v[j].z - mu) * rstd * gg.z + bb.z;
        o.w = (v[j].w - mu) * rstd * gg.w + bb.w;
        *(float4*)&p[lane * 4 + j * 128] = o;
    }
}

// ============================================================================
// Launch
// ============================================================================
#define SMEM_LIN_TOT (2 * 128 * PS * 2 + 2 * 128 * PS * 2)        /* 73728 */
#define SMEM_F0  (128 * PS * 2 + 2 * 128 * PS * 2 + 1024)         /* 56320 */
#define SMEM_F1  (18432 + 27648 + 27648 + 512)                    /* 74240 */

extern "C" void kernel_launch(void* const* d_in, const int* in_sizes, int n_in,
                              void* d_out, int out_size)
{
    const float* q   = (const float*)d_in[0];
    const float* k   = (const float*)d_in[1];
    const float* v   = (const float*)d_in[2];
    const float* Wq  = (const float*)d_in[3];
    const float* bq  = (const float*)d_in[4];
    const float* Wk  = (const float*)d_in[5];
    const float* bk  = (const float*)d_in[6];
    const float* Wv  = (const float*)d_in[7];
    const float* bv  = (const float*)d_in[8];
    const float* Wo  = (const float*)d_in[9];
    const float* bo  = (const float*)d_in[10];
    const float* lng = (const float*)d_in[11];
    const float* lnb = (const float*)d_in[12];

    float* out = (float*)d_out;

    float *qlin, *attn_scr, *rowsum;
    __half *qh, *kh, *vh, *ctxh, *inqh, *inkh, *invh, *Wqh, *Wkh, *Wvh, *Woh;
    cudaGetSymbolAddress((void**)&qlin, g_qlin);
    cudaGetSymbolAddress((void**)&attn_scr, g_attn_scratch);
    cudaGetSymbolAddress((void**)&rowsum, g_rowsum);
    cudaGetSymbolAddress((void**)&qh, g_qh);
    cudaGetSymbolAddress((void**)&kh, g_kh);
    cudaGetSymbolAddress((void**)&vh, g_vh);
    cudaGetSymbolAddress((void**)&ctxh, g_ctxh);
    cudaGetSymbolAddress((void**)&inqh, g_inqh);
    cudaGetSymbolAddress((void**)&inkh, g_inkh);
    cudaGetSymbolAddress((void**)&invh, g_invh);
    cudaGetSymbolAddress((void**)&Wqh, g_Wqh);
    cudaGetSymbolAddress((void**)&Wkh, g_Wkh);
    cudaGetSymbolAddress((void**)&Wvh, g_Wvh);
    cudaGetSymbolAddress((void**)&Woh, g_Woh);

    float* attn = ((size_t)out_size >= OUT_ELEMS + ATTN_ELEMS)
                      ? out + OUT_ELEMS : attn_scr;

    cudaFuncSetAttribute((const void*)qkv_kernel,
                         cudaFuncAttributeMaxDynamicSharedMemorySize, SMEM_LIN_TOT);
    cudaFuncSetAttribute((const void*)outproj_kernel,
                         cudaFuncAttributeMaxDynamicSharedMemorySize, SMEM_LIN_TOT);
    cudaFuncSetAttribute((const void*)flash0_kernel,
                         cudaFuncAttributeMaxDynamicSharedMemorySize, SMEM_F0);
    cudaFuncSetAttribute((const void*)flash1_kernel,
                         cudaFuncAttributeMaxDynamicSharedMemorySize, SMEM_F1);

    dim3 blk(256);

    // 0) fp16 conversions (2 launches)
    const int NIN4 = (BB * SQ * DD) / 4;
    const int NW4  = (DD * DD) / 4;
    to_half3_kernel<<<dim3((NIN4 + 255) / 256, 3), blk>>>(q, k, v, inqh, inkh, invh, NIN4);
    to_half4_kernel<<<dim3((NW4 + 255) / 256, 4), blk>>>(Wq, Wk, Wv, Wo,
                                                         Wqh, Wkh, Wvh, Woh, NW4);

    // 1) merged QKV projections (one launch, 384 CTAs)
    dim3 gQKV(DD / 128, (BB * SQ) / 128, 3);
    qkv_kernel<<<gQKV, blk, SMEM_LIN_TOT>>>(inqh, inkh, invh, Wqh, Wkh, Wvh,
                                            bq, bk, bv, qlin, qh, kh, vh);

    // 2) pass A: row sums (kv tile 128)
    dim3 gFl(SQ / 128, BB * HH);
    flash0_kernel<<<gFl, blk, SMEM_F0>>>(qh, kh, rowsum);

    // 3) pass B: normalized attn + O = P@V (register-fragment reuse)
    flash1_kernel<<<gFl, blk, SMEM_F1>>>(qh, kh, vh, rowsum, attn, ctxh);

    // 4) output projection + residual(q_lin)
    dim3 gLin(DD / 128, (BB * SQ) / 128);
    outproj_kernel<<<gLin, blk, SMEM_LIN_TOT>>>(ctxh, Woh, bo, qlin, out);

    // 5) layernorm (warp per row)
    ln_kernel<<<(BB * SQ) / 8, blk>>>(out, lng, lnb);
}